// round 5
// baseline (speedup 1.0000x reference)
#include <cuda_runtime.h>
#include <cuda_fp16.h>
#include <cstddef>

#define N_NODES 50000
#define NC 128
#define NE 800000
#define NS 8
#define NH 64
#define NB_ 8
#define LN_EPS 1e-5f
#define SCAN_NB 13
#define SCAN_CHUNK 4096

// ---------------- scratch (device globals; no allocation) ----------------
__device__ int    g_off [3][N_NODES + 1];
__device__ int    g_pos [3][N_NODES];      // degree hist -> write cursors
__device__ int    g_bsum[3][SCAN_NB];
__device__ int    g_srcs[3][NE];
__device__ float  g_mid_a[(size_t)N_NODES * 256];
__device__ float  g_mid_b[(size_t)N_NODES * NC];
__device__ __half g_ha[(size_t)N_NODES * NC];
__device__ __half g_hb[(size_t)N_NODES * NC];
__device__ float  g_Wab [2][NC * NC];
__device__ float  g_Wcat[2][NC * 256];     // [j][0:128]=W_ba  [j][128:256]=W_aa
__device__ float  g_coeff[3][NB_];         // 0: ab, 1: ba, 2: aa

// ---------------- CSR build ----------------
__global__ void hist3_kernel(const int* __restrict__ e0, const int* __restrict__ e1,
                             const int* __restrict__ e2) {
    int i = blockIdx.x * blockDim.x + threadIdx.x;  // grid covers exactly 3*NE
    int t = i / NE, j = i % NE;
    const int* e = (t == 0) ? e0 : (t == 1) ? e1 : e2;
    atomicAdd(&g_pos[t][e[NE + j]], 1);
}

__global__ void scan1_kernel() {           // grid = 3*SCAN_NB, block = 1024
    int t = blockIdx.x / SCAN_NB, c = blockIdx.x % SCAN_NB;
    int base = c * SCAN_CHUNK;
    int tid = threadIdx.x;
    int v = 0;
#pragma unroll
    for (int i = 0; i < 4; i++) {
        int idx = base + tid * 4 + i;
        if (idx < N_NODES) v += g_pos[t][idx];
    }
#pragma unroll
    for (int o = 16; o > 0; o >>= 1) v += __shfl_xor_sync(0xffffffffu, v, o);
    __shared__ int ws[32];
    if ((tid & 31) == 0) ws[tid >> 5] = v;
    __syncthreads();
    if (tid < 32) {
        int s = (tid < 32) ? ws[tid] : 0;
#pragma unroll
        for (int o = 16; o > 0; o >>= 1) s += __shfl_xor_sync(0xffffffffu, s, o);
        if (tid == 0) g_bsum[t][c] = s;
    }
}

__global__ void scan2_kernel() {           // 1 block, 1 thread does 39 adds
    if (threadIdx.x == 0) {
        for (int t = 0; t < 3; t++) {
            int run = 0;
            for (int c = 0; c < SCAN_NB; c++) {
                int v = g_bsum[t][c];
                g_bsum[t][c] = run;
                run += v;
            }
            g_off[t][N_NODES] = run;
        }
    }
}

__global__ void scan3_kernel() {           // grid = 3*SCAN_NB, block = 1024
    int t = blockIdx.x / SCAN_NB, c = blockIdx.x % SCAN_NB;
    int base = c * SCAN_CHUNK;
    int tid = threadIdx.x, lane = tid & 31, wid = tid >> 5;
    int v[4], s = 0;
#pragma unroll
    for (int i = 0; i < 4; i++) {
        int idx = base + tid * 4 + i;
        v[i] = (idx < N_NODES) ? g_pos[t][idx] : 0;
        s += v[i];
    }
    int si = s;
#pragma unroll
    for (int d = 1; d < 32; d <<= 1) {
        int n = __shfl_up_sync(0xffffffffu, si, d);
        if (lane >= d) si += n;
    }
    __shared__ int ws[32];
    if (lane == 31) ws[wid] = si;
    __syncthreads();
    if (wid == 0) {
        int w = ws[lane];
#pragma unroll
        for (int d = 1; d < 32; d <<= 1) {
            int n = __shfl_up_sync(0xffffffffu, w, d);
            if (lane >= d) w += n;
        }
        ws[lane] = w;
    }
    __syncthreads();
    int run = si - s + (wid ? ws[wid - 1] : 0) + g_bsum[t][c];
#pragma unroll
    for (int i = 0; i < 4; i++) {
        int idx = base + tid * 4 + i;
        if (idx < N_NODES) {
            g_off[t][idx] = run;
            g_pos[t][idx] = run;
            run += v[i];
        }
    }
}

__global__ void fill3_kernel(const int* __restrict__ e0, const int* __restrict__ e1,
                             const int* __restrict__ e2) {
    int i = blockIdx.x * blockDim.x + threadIdx.x;
    int t = i / NE, j = i % NE;
    const int* e = (t == 0) ? e0 : (t == 1) ? e1 : e2;
    int s = e[j], d = e[NE + j];
    int p = atomicAdd(&g_pos[t][d], 1);
    g_srcs[t][p] = s;
}

// ---------------- fp16 copies of the input tables ----------------
__device__ __forceinline__ unsigned pack2(float a, float b) {
    __half2 h = __floats2half2_rn(a, b);
    return *(unsigned*)&h;
}

__global__ void tohalf_kernel(const float* __restrict__ xa, const float* __restrict__ xb) {
    int i = blockIdx.x * blockDim.x + threadIdx.x;   // each handles 8 floats
    const size_t TOT = (size_t)N_NODES * NC;
    size_t base = (size_t)i * 8;
    const float* src;
    __half* dst;
    if (base < TOT) { src = xa + base; dst = g_ha + base; }
    else            { src = xb + (base - TOT); dst = g_hb + (base - TOT); }
    float4 v0 = *(const float4*)src;
    float4 v1 = *(const float4*)(src + 4);
    uint4 u = make_uint4(pack2(v0.x, v0.y), pack2(v0.z, v0.w),
                         pack2(v1.x, v1.y), pack2(v1.z, v1.w));
    *(uint4*)dst = u;
}

// ---------------- schema GCN + dynamic coefficients ----------------
__global__ void schema_kernel(const float* __restrict__ schema_x, const int* __restrict__ sei,
                              const float* __restrict__ pre_W, const float* __restrict__ pre_b,
                              const float* __restrict__ gcn_W, const float* __restrict__ gcn_b,
                              const float* __restrict__ coeff_W, const float* __restrict__ coeff_b,
                              float* __restrict__ out_sf, float* __restrict__ out_ori) {
    __shared__ float h [NS][NH];
    __shared__ float xw[NS][NH];
    __shared__ float sf[NS][NH];
    __shared__ float dinv[NS];
    int tid = threadIdx.x;              // 512 = 8*64
    int s = tid / NH, j = tid % NH;

    float acc = pre_b[j];
    for (int i = 0; i < NH; i++) acc += schema_x[s * NH + i] * pre_W[j * NH + i];
    h[s][j] = acc;
    out_ori[s * NH + j] = acc;
    __syncthreads();

    float xacc = 0.f;
    for (int k = 0; k < NH; k++) xacc += h[s][k] * gcn_W[j * NH + k];
    xw[s][j] = xacc;
    if (tid < NS) {
        float d = 1.0f;
        for (int e = 0; e < 24; e++) if (sei[24 + e] == tid) d += 1.0f;
        dinv[tid] = rsqrtf(fmaxf(d, 1e-12f));
    }
    __syncthreads();

    float o = gcn_b[j] + dinv[s] * dinv[s] * xw[s][j];
    for (int e = 0; e < 24; e++) {
        int es = sei[e], ed = sei[24 + e];
        if (ed == s) o += dinv[es] * dinv[s] * xw[es][j];
    }
    o = fmaxf(o, 0.f);
    sf[s][j] = o;
    out_sf[s * NH + j] = o;
    __syncthreads();

    if (tid < 3 * NB_) {
        int t = tid / NB_, i = tid % NB_;
        int ssrc = (t == 1) ? 1 : 0;
        int sdst = (t == 0) ? 1 : 0;
        float c = coeff_b[i];
        for (int k = 0; k < NH; k++) c += sf[ssrc][k] * coeff_W[i * 128 + k];
        for (int k = 0; k < NH; k++) c += sf[sdst][k] * coeff_W[i * 128 + 64 + k];
        g_coeff[t][i] = c;
    }
}

__global__ void buildW_kernel(const float* __restrict__ bases) {
    int id = blockIdx.x * blockDim.x + threadIdx.x;
    if (id >= 2 * NC * NC) return;
    int l = id / (NC * NC);
    int jk = id % (NC * NC);
    int j = jk / NC, k = jk % NC;
    float wab = 0.f, wba = 0.f, waa = 0.f;
#pragma unroll
    for (int i = 0; i < NB_; i++) {
        float b = bases[(size_t)l * NB_ * NC * NC + (size_t)i * NC * NC + jk];
        wab += g_coeff[0][i] * b;
        wba += g_coeff[1][i] * b;
        waa += g_coeff[2][i] * b;
    }
    g_Wab[l][jk] = wab;
    g_Wcat[l][j * 256 + k] = wba;
    g_Wcat[l][j * 256 + 128 + k] = waa;
}

// ---------------- aggregation (fp16 sources, fp32 accum) ----------------
__device__ __forceinline__ void add_row(const __half* __restrict__ p, float4& a) {
    uint2 u = *(const uint2*)p;
    __half2 h0 = *(__half2*)&u.x, h1 = *(__half2*)&u.y;
    float2 f0 = __half22float2(h0), f1 = __half22float2(h1);
    a.x += f0.x; a.y += f0.y; a.z += f1.x; a.w += f1.y;
}

__device__ __forceinline__ void acc_range(const __half* __restrict__ xsrc,
                                          const int* __restrict__ srcs,
                                          int beg, int end, int col, float4& out) {
    float4 a0 = make_float4(0, 0, 0, 0), a1 = a0;
    int e = beg;
    for (; e + 2 <= end; e += 2) {
        int s0 = srcs[e], s1 = srcs[e + 1];
        add_row(xsrc + (size_t)s0 * NC + col, a0);
        add_row(xsrc + (size_t)s1 * NC + col, a1);
    }
    if (e < end) add_row(xsrc + (size_t)srcs[e] * NC + col, a0);
    float inv = 1.0f / fmaxf((float)(end - beg), 1.0f);
    out.x = (a0.x + a1.x) * inv;
    out.y = (a0.y + a1.y) * inv;
    out.z = (a0.z + a1.z) * inv;
    out.w = (a0.w + a1.w) * inv;
}

// ab edges: src=ha, dst=hb -> mid_b [N,128]
__global__ void agg_b_kernel(const __half* __restrict__ ha, const __half* __restrict__ hb,
                             float* __restrict__ mid) {
    int g = blockIdx.x * blockDim.x + threadIdx.x;
    int node = g >> 5, lane = g & 31;
    if (node >= N_NODES) return;
    int col = lane * 4;
    float4 m;
    acc_range(ha, g_srcs[0], g_off[0][node], g_off[0][node + 1], col, m);
    float4 xd = make_float4(0, 0, 0, 0);
    add_row(hb + (size_t)node * NC + col, xd);
    m.x += xd.x; m.y += xd.y; m.z += xd.z; m.w += xd.w;
    *(float4*)(mid + (size_t)node * NC + col) = m;
}

// ba (src=hb) + aa (src=ha) edges, dst=ha -> mid_a [N,256]
__global__ void agg_a_kernel(const __half* __restrict__ ha, const __half* __restrict__ hb,
                             float* __restrict__ mid) {
    int g = blockIdx.x * blockDim.x + threadIdx.x;
    int node = g >> 5, lane = g & 31;
    if (node >= N_NODES) return;
    int col = lane * 4;
    float4 xd = make_float4(0, 0, 0, 0);
    add_row(ha + (size_t)node * NC + col, xd);
    float4 m0, m1;
    acc_range(hb, g_srcs[1], g_off[1][node], g_off[1][node + 1], col, m0);
    acc_range(ha, g_srcs[2], g_off[2][node], g_off[2][node + 1], col, m1);
    m0.x += xd.x; m0.y += xd.y; m0.z += xd.z; m0.w += xd.w;
    m1.x += xd.x; m1.y += xd.y; m1.z += xd.z; m1.w += xd.w;
    *(float4*)(mid + (size_t)node * 256 + col) = m0;
    *(float4*)(mid + (size_t)node * 256 + 128 + col) = m1;
}

// ---------------- tf32 GEMM + bias + LayerNorm + ReLU fused ----------------
__device__ __forceinline__ float tf32r(float x) {
    unsigned u;
    asm("cvt.rna.tf32.f32 %0, %1;" : "=r"(u) : "f"(x));
    return __uint_as_float(u);
}

#define APITCH 36
#define OPITCH 132

template <int K>
__global__ void __launch_bounds__(256)
gemm_ln_kernel(const float* __restrict__ A, const float* __restrict__ W,
               const float* __restrict__ b1, const float* __restrict__ b2,
               const float* __restrict__ lw, const float* __restrict__ lb,
               float* __restrict__ out, __half* __restrict__ hout, int M) {
    extern __shared__ float buf[];           // max(2*128*36, 128*132) = 16896 floats
    float* At = buf;                         // [128][36]
    float* Wt = buf + 128 * APITCH;
    __shared__ float sb[3][NC];

    int tid = threadIdx.x;
    int lane = tid & 31, wid = tid >> 5;
    int warp_m = wid >> 2, warp_n = wid & 3; // 2 x 4 warps
    int gid = lane >> 2, tig = lane & 3;
    int row0 = blockIdx.x * 128;

    if (tid < NC) {
        float c = b1[tid];
        if (b2) c += b2[tid];
        sb[0][tid] = c;
        sb[1][tid] = lw[tid];
        sb[2][tid] = lb[tid];
    }

    float acc[4][4][4];
#pragma unroll
    for (int i = 0; i < 4; i++)
#pragma unroll
        for (int j = 0; j < 4; j++)
#pragma unroll
            for (int c = 0; c < 4; c++) acc[i][j][c] = 0.f;

    for (int kc = 0; kc < K; kc += 32) {
#pragma unroll
        for (int it = 0; it < 4; it++) {
            int idx = tid + it * 256;        // 0..1023
            int r = idx >> 3, seg = idx & 7;
            float4 v = make_float4(0, 0, 0, 0);
            if (row0 + r < M)
                v = *(const float4*)(A + (size_t)(row0 + r) * K + kc + seg * 4);
            float* dp = At + r * APITCH + seg * 4;
            dp[0] = tf32r(v.x); dp[1] = tf32r(v.y); dp[2] = tf32r(v.z); dp[3] = tf32r(v.w);
            float4 w4 = *(const float4*)(W + (size_t)r * K + kc + seg * 4);
            float* dw = Wt + r * APITCH + seg * 4;
            dw[0] = tf32r(w4.x); dw[1] = tf32r(w4.y); dw[2] = tf32r(w4.z); dw[3] = tf32r(w4.w);
        }
        __syncthreads();
#pragma unroll
        for (int ks = 0; ks < 4; ks++) {
            int k = ks * 8;
            unsigned bfr[4][2];
#pragma unroll
            for (int j = 0; j < 4; j++) {
                int n0 = warp_n * 32 + j * 8;
                bfr[j][0] = __float_as_uint(Wt[(n0 + gid) * APITCH + k + tig]);
                bfr[j][1] = __float_as_uint(Wt[(n0 + gid) * APITCH + k + tig + 4]);
            }
#pragma unroll
            for (int i = 0; i < 4; i++) {
                int m0 = warp_m * 64 + i * 16;
                unsigned a0 = __float_as_uint(At[(m0 + gid) * APITCH + k + tig]);
                unsigned a1 = __float_as_uint(At[(m0 + gid + 8) * APITCH + k + tig]);
                unsigned a2 = __float_as_uint(At[(m0 + gid) * APITCH + k + tig + 4]);
                unsigned a3 = __float_as_uint(At[(m0 + gid + 8) * APITCH + k + tig + 4]);
#pragma unroll
                for (int j = 0; j < 4; j++) {
                    asm volatile(
                        "mma.sync.aligned.m16n8k8.row.col.f32.tf32.tf32.f32 "
                        "{%0,%1,%2,%3}, {%4,%5,%6,%7}, {%8,%9}, {%0,%1,%2,%3};\n"
                        : "+f"(acc[i][j][0]), "+f"(acc[i][j][1]),
                          "+f"(acc[i][j][2]), "+f"(acc[i][j][3])
                        : "r"(a0), "r"(a1), "r"(a2), "r"(a3),
                          "r"(bfr[j][0]), "r"(bfr[j][1]));
                }
            }
        }
        __syncthreads();
    }

    float* Ot = buf;                         // [128][132] aliases At/Wt
#pragma unroll
    for (int i = 0; i < 4; i++) {
        int m0 = warp_m * 64 + i * 16;
#pragma unroll
        for (int j = 0; j < 4; j++) {
            int n0 = warp_n * 32 + j * 8 + 2 * tig;
            Ot[(m0 + gid) * OPITCH + n0]         = acc[i][j][0];
            Ot[(m0 + gid) * OPITCH + n0 + 1]     = acc[i][j][1];
            Ot[(m0 + gid + 8) * OPITCH + n0]     = acc[i][j][2];
            Ot[(m0 + gid + 8) * OPITCH + n0 + 1] = acc[i][j][3];
        }
    }
    __syncthreads();

    int col = lane * 4;
    for (int rr = 0; rr < 16; rr++) {
        int r = wid * 16 + rr;
        int grow = row0 + r;
        if (grow >= M) break;
        float4 v = *(const float4*)&Ot[r * OPITCH + col];
        v.x += sb[0][col];     v.y += sb[0][col + 1];
        v.z += sb[0][col + 2]; v.w += sb[0][col + 3];
        float s = v.x + v.y + v.z + v.w;
#pragma unroll
        for (int o = 16; o > 0; o >>= 1) s += __shfl_xor_sync(0xffffffffu, s, o);
        float mu = s * (1.0f / NC);
        float dx = v.x - mu, dy = v.y - mu, dz = v.z - mu, dw = v.w - mu;
        float q = dx * dx + dy * dy + dz * dz + dw * dw;
#pragma unroll
        for (int o = 16; o > 0; o >>= 1) q += __shfl_xor_sync(0xffffffffu, q, o);
        float rs = rsqrtf(q * (1.0f / NC) + LN_EPS);
        float4 y;
        y.x = fmaxf(dx * rs * sb[1][col]     + sb[2][col],     0.f);
        y.y = fmaxf(dy * rs * sb[1][col + 1] + sb[2][col + 1], 0.f);
        y.z = fmaxf(dz * rs * sb[1][col + 2] + sb[2][col + 2], 0.f);
        y.w = fmaxf(dw * rs * sb[1][col + 3] + sb[2][col + 3], 0.f);
        if (out) *(float4*)(out + (size_t)grow * NC + col) = y;
        if (hout) {
            uint2 u = make_uint2(pack2(y.x, y.y), pack2(y.z, y.w));
            *(uint2*)(hout + (size_t)grow * NC + col) = u;
        }
    }
}

// ---------------- launch ----------------
extern "C" void kernel_launch(void* const* d_in, const int* in_sizes, int n_in,
                              void* d_out, int out_size) {
    (void)in_sizes; (void)n_in; (void)out_size;
    const float* x_a      = (const float*)d_in[0];
    const float* x_b      = (const float*)d_in[1];
    const float* schema_x = (const float*)d_in[2];
    const int*   e_ab     = (const int*)d_in[3];
    const int*   e_ba     = (const int*)d_in[4];
    const int*   e_aa     = (const int*)d_in[5];
    const int*   sei      = (const int*)d_in[6];
    const float* pre_W    = (const float*)d_in[7];
    const float* pre_b    = (const float*)d_in[8];
    const float* gcn_W    = (const float*)d_in[9];
    const float* gcn_b    = (const float*)d_in[10];
    const float* coeff_W  = (const float*)d_in[11];
    const float* coeff_b  = (const float*)d_in[12];
    const float* bases    = (const float*)d_in[13];
    const float* sage_bias= (const float*)d_in[14];
    const float* ln_w     = (const float*)d_in[15];
    const float* ln_b     = (const float*)d_in[16];

    float* out = (float*)d_out;
    float* out_xa  = out;
    float* out_xb  = out + (size_t)N_NODES * NC;
    float* out_sf  = out + (size_t)2 * N_NODES * NC;
    float* out_ori = out_sf + NS * NH;

    float *p_mid_a, *p_mid_b, *p_Wab, *p_Wcat;
    int* p_pos;
    __half *p_ha, *p_hb;
    cudaGetSymbolAddress((void**)&p_mid_a, g_mid_a);
    cudaGetSymbolAddress((void**)&p_mid_b, g_mid_b);
    cudaGetSymbolAddress((void**)&p_ha,    g_ha);
    cudaGetSymbolAddress((void**)&p_hb,    g_hb);
    cudaGetSymbolAddress((void**)&p_Wab,   g_Wab);
    cudaGetSymbolAddress((void**)&p_Wcat,  g_Wcat);
    cudaGetSymbolAddress((void**)&p_pos,   g_pos);

    const int SMEM_GEMM = 16896 * sizeof(float);
    cudaFuncSetAttribute(gemm_ln_kernel<256>,
                         cudaFuncAttributeMaxDynamicSharedMemorySize, SMEM_GEMM);
    cudaFuncSetAttribute(gemm_ln_kernel<128>,
                         cudaFuncAttributeMaxDynamicSharedMemorySize, SMEM_GEMM);

    // ---- CSR build ----
    cudaMemsetAsync(p_pos, 0, sizeof(int) * 3 * N_NODES);
    hist3_kernel<<<3 * NE / 256, 256>>>(e_ab, e_ba, e_aa);
    scan1_kernel<<<3 * SCAN_NB, 1024>>>();
    scan2_kernel<<<1, 32>>>();
    scan3_kernel<<<3 * SCAN_NB, 1024>>>();
    fill3_kernel<<<3 * NE / 256, 256>>>(e_ab, e_ba, e_aa);

    // ---- schema + dynamic weights + fp16 input copies ----
    schema_kernel<<<1, 512>>>(schema_x, sei, pre_W, pre_b, gcn_W, gcn_b,
                              coeff_W, coeff_b, out_sf, out_ori);
    buildW_kernel<<<(2 * NC * NC + 255) / 256, 256>>>(bases);
    tohalf_kernel<<<(2 * N_NODES * NC / 8) / 256, 256>>>(x_a, x_b);

    const int AGG_GRID  = (N_NODES * 32 + 255) / 256;
    const int GEMM_GRID = (N_NODES + 127) / 128;

    // ---- layer 0 (outputs only needed in fp16 for layer 1) ----
    agg_b_kernel<<<AGG_GRID, 256>>>(p_ha, p_hb, p_mid_b);
    agg_a_kernel<<<AGG_GRID, 256>>>(p_ha, p_hb, p_mid_a);
    gemm_ln_kernel<256><<<GEMM_GRID, 256, SMEM_GEMM>>>(
        p_mid_a, p_Wcat, sage_bias + 1 * NC, sage_bias + 2 * NC,
        ln_w + 0 * NC, ln_b + 0 * NC, nullptr, p_ha, N_NODES);
    gemm_ln_kernel<128><<<GEMM_GRID, 256, SMEM_GEMM>>>(
        p_mid_b, p_Wab, sage_bias + 0 * NC, nullptr,
        ln_w + 1 * NC, ln_b + 1 * NC, nullptr, p_hb, N_NODES);

    // ---- layer 1 (fp32 outputs to d_out) ----
    agg_b_kernel<<<AGG_GRID, 256>>>(p_ha, p_hb, p_mid_b);
    agg_a_kernel<<<AGG_GRID, 256>>>(p_ha, p_hb, p_mid_a);
    gemm_ln_kernel<256><<<GEMM_GRID, 256, SMEM_GEMM>>>(
        p_mid_a, p_Wcat + NC * 256, sage_bias + 4 * NC, sage_bias + 5 * NC,
        ln_w + 2 * NC, ln_b + 2 * NC, out_xa, nullptr, N_NODES);
    gemm_ln_kernel<128><<<GEMM_GRID, 256, SMEM_GEMM>>>(
        p_mid_b, p_Wab + NC * NC, sage_bias + 3 * NC, nullptr,
        ln_w + 3 * NC, ln_b + 3 * NC, out_xb, nullptr, N_NODES);
}

// round 6
// speedup vs baseline: 1.0038x; 1.0038x over previous
#include <cuda_runtime.h>
#include <cstddef>

#define N_NODES 50000
#define NC 128
#define NE 800000
#define NS 8
#define NH 64
#define NB_ 8
#define LN_EPS 1e-5f
#define SCAN_NB 13
#define SCAN_CHUNK 4096

// ---------------- scratch (device globals; no allocation) ----------------
__device__ int   g_off [3][N_NODES + 1];
__device__ int   g_pos [3][N_NODES];       // degree hist -> write cursors
__device__ int   g_bsum[3][SCAN_NB];
__device__ int   g_srcs[3][NE];
__device__ float g_mid_a[(size_t)N_NODES * 256];
__device__ float g_mid_b[(size_t)N_NODES * NC];
__device__ float g_xa   [(size_t)N_NODES * NC];
__device__ float g_xb   [(size_t)N_NODES * NC];
__device__ float g_Wab [2][NC * NC];
__device__ float g_Wcat[2][NC * 256];      // [j][0:128]=W_ba  [j][128:256]=W_aa
__device__ float g_coeff[3][NB_];          // 0: ab, 1: ba, 2: aa

// ---------------- CSR build ----------------
__global__ void hist3_kernel(const int* __restrict__ e0, const int* __restrict__ e1,
                             const int* __restrict__ e2) {
    int i = blockIdx.x * blockDim.x + threadIdx.x;  // grid covers exactly 3*NE
    int t = i / NE, j = i % NE;
    const int* e = (t == 0) ? e0 : (t == 1) ? e1 : e2;
    atomicAdd(&g_pos[t][e[NE + j]], 1);
}

__global__ void scan1_kernel() {           // grid = 3*SCAN_NB, block = 1024
    int t = blockIdx.x / SCAN_NB, c = blockIdx.x % SCAN_NB;
    int base = c * SCAN_CHUNK;
    int tid = threadIdx.x;
    int v = 0;
#pragma unroll
    for (int i = 0; i < 4; i++) {
        int idx = base + tid * 4 + i;
        if (idx < N_NODES) v += g_pos[t][idx];
    }
#pragma unroll
    for (int o = 16; o > 0; o >>= 1) v += __shfl_xor_sync(0xffffffffu, v, o);
    __shared__ int ws[32];
    if ((tid & 31) == 0) ws[tid >> 5] = v;
    __syncthreads();
    if (tid < 32) {
        int s = ws[tid];
#pragma unroll
        for (int o = 16; o > 0; o >>= 1) s += __shfl_xor_sync(0xffffffffu, s, o);
        if (tid == 0) g_bsum[t][c] = s;
    }
}

__global__ void scan2_kernel() {
    if (threadIdx.x == 0) {
        for (int t = 0; t < 3; t++) {
            int run = 0;
            for (int c = 0; c < SCAN_NB; c++) {
                int v = g_bsum[t][c];
                g_bsum[t][c] = run;
                run += v;
            }
            g_off[t][N_NODES] = run;
        }
    }
}

__global__ void scan3_kernel() {           // grid = 3*SCAN_NB, block = 1024
    int t = blockIdx.x / SCAN_NB, c = blockIdx.x % SCAN_NB;
    int base = c * SCAN_CHUNK;
    int tid = threadIdx.x, lane = tid & 31, wid = tid >> 5;
    int v[4], s = 0;
#pragma unroll
    for (int i = 0; i < 4; i++) {
        int idx = base + tid * 4 + i;
        v[i] = (idx < N_NODES) ? g_pos[t][idx] : 0;
        s += v[i];
    }
    int si = s;
#pragma unroll
    for (int d = 1; d < 32; d <<= 1) {
        int n = __shfl_up_sync(0xffffffffu, si, d);
        if (lane >= d) si += n;
    }
    __shared__ int ws[32];
    if (lane == 31) ws[wid] = si;
    __syncthreads();
    if (wid == 0) {
        int w = ws[lane];
#pragma unroll
        for (int d = 1; d < 32; d <<= 1) {
            int n = __shfl_up_sync(0xffffffffu, w, d);
            if (lane >= d) w += n;
        }
        ws[lane] = w;
    }
    __syncthreads();
    int run = si - s + (wid ? ws[wid - 1] : 0) + g_bsum[t][c];
#pragma unroll
    for (int i = 0; i < 4; i++) {
        int idx = base + tid * 4 + i;
        if (idx < N_NODES) {
            g_off[t][idx] = run;
            g_pos[t][idx] = run;
            run += v[i];
        }
    }
}

__global__ void fill3_kernel(const int* __restrict__ e0, const int* __restrict__ e1,
                             const int* __restrict__ e2) {
    int i = blockIdx.x * blockDim.x + threadIdx.x;
    int t = i / NE, j = i % NE;
    const int* e = (t == 0) ? e0 : (t == 1) ? e1 : e2;
    int s = e[j], d = e[NE + j];
    int p = atomicAdd(&g_pos[t][d], 1);
    g_srcs[t][p] = s;
}

// ---------------- schema GCN + dynamic coefficients (1 block, 512 thr) ----------------
__global__ void schema_kernel(const float* __restrict__ schema_x, const int* __restrict__ sei,
                              const float* __restrict__ pre_W, const float* __restrict__ pre_b,
                              const float* __restrict__ gcn_W, const float* __restrict__ gcn_b,
                              const float* __restrict__ coeff_W, const float* __restrict__ coeff_b,
                              float* __restrict__ out_sf, float* __restrict__ out_ori) {
    __shared__ float h [NS][NH];
    __shared__ float xw[NS][NH];
    __shared__ float sf[NS][NH];
    __shared__ float dinv[NS];
    int tid = threadIdx.x;              // 512 = 8*64
    int s = tid / NH, j = tid % NH;

    float acc = pre_b[j];
    for (int i = 0; i < NH; i++) acc += schema_x[s * NH + i] * pre_W[j * NH + i];
    h[s][j] = acc;
    out_ori[s * NH + j] = acc;
    __syncthreads();

    float xacc = 0.f;
    for (int k = 0; k < NH; k++) xacc += h[s][k] * gcn_W[j * NH + k];
    xw[s][j] = xacc;
    if (tid < NS) {
        float d = 1.0f;
        for (int e = 0; e < 24; e++) if (sei[24 + e] == tid) d += 1.0f;
        dinv[tid] = rsqrtf(fmaxf(d, 1e-12f));
    }
    __syncthreads();

    float o = gcn_b[j] + dinv[s] * dinv[s] * xw[s][j];
    for (int e = 0; e < 24; e++) {
        int es = sei[e], ed = sei[24 + e];
        if (ed == s) o += dinv[es] * dinv[s] * xw[es][j];
    }
    o = fmaxf(o, 0.f);
    sf[s][j] = o;
    out_sf[s * NH + j] = o;
    __syncthreads();

    if (tid < 3 * NB_) {
        int t = tid / NB_, i = tid % NB_;
        int ssrc = (t == 1) ? 1 : 0;
        int sdst = (t == 0) ? 1 : 0;
        float c = coeff_b[i];
        for (int k = 0; k < NH; k++) c += sf[ssrc][k] * coeff_W[i * 128 + k];
        for (int k = 0; k < NH; k++) c += sf[sdst][k] * coeff_W[i * 128 + 64 + k];
        g_coeff[t][i] = c;
    }
}

__global__ void buildW_kernel(const float* __restrict__ bases) {
    int id = blockIdx.x * blockDim.x + threadIdx.x;
    if (id >= 2 * NC * NC) return;
    int l = id / (NC * NC);
    int jk = id % (NC * NC);
    int j = jk / NC, k = jk % NC;
    float wab = 0.f, wba = 0.f, waa = 0.f;
#pragma unroll
    for (int i = 0; i < NB_; i++) {
        float b = bases[(size_t)l * NB_ * NC * NC + (size_t)i * NC * NC + jk];
        wab += g_coeff[0][i] * b;
        wba += g_coeff[1][i] * b;
        waa += g_coeff[2][i] * b;
    }
    g_Wab[l][jk] = wab;
    g_Wcat[l][j * 256 + k] = wba;
    g_Wcat[l][j * 256 + 128 + k] = waa;
}

// ---------------- aggregation: warp per destination node, MLP=4 ----------------
__device__ __forceinline__ void acc_range(const float* __restrict__ xsrc,
                                          const int* __restrict__ srcs,
                                          int beg, int end, int col, float4& out) {
    float4 a0 = make_float4(0, 0, 0, 0), a1 = a0, a2 = a0, a3 = a0;
    int e = beg;
    for (; e + 4 <= end; e += 4) {
        int s0 = srcs[e], s1 = srcs[e + 1], s2 = srcs[e + 2], s3 = srcs[e + 3];
        float4 v0 = *(const float4*)(xsrc + (size_t)s0 * NC + col);
        float4 v1 = *(const float4*)(xsrc + (size_t)s1 * NC + col);
        float4 v2 = *(const float4*)(xsrc + (size_t)s2 * NC + col);
        float4 v3 = *(const float4*)(xsrc + (size_t)s3 * NC + col);
        a0.x += v0.x; a0.y += v0.y; a0.z += v0.z; a0.w += v0.w;
        a1.x += v1.x; a1.y += v1.y; a1.z += v1.z; a1.w += v1.w;
        a2.x += v2.x; a2.y += v2.y; a2.z += v2.z; a2.w += v2.w;
        a3.x += v3.x; a3.y += v3.y; a3.z += v3.z; a3.w += v3.w;
    }
    for (; e < end; e++) {
        int s0 = srcs[e];
        float4 v0 = *(const float4*)(xsrc + (size_t)s0 * NC + col);
        a0.x += v0.x; a0.y += v0.y; a0.z += v0.z; a0.w += v0.w;
    }
    float inv = 1.0f / fmaxf((float)(end - beg), 1.0f);
    out.x = (a0.x + a1.x + a2.x + a3.x) * inv;
    out.y = (a0.y + a1.y + a2.y + a3.y) * inv;
    out.z = (a0.z + a1.z + a2.z + a3.z) * inv;
    out.w = (a0.w + a1.w + a2.w + a3.w) * inv;
}

// ab edges: src=x_a, dst=x_b -> mid_b [N,128]
__global__ void agg_b_kernel(const float* __restrict__ xa, const float* __restrict__ xb,
                             float* __restrict__ mid) {
    int g = blockIdx.x * blockDim.x + threadIdx.x;
    int node = g >> 5, lane = g & 31;
    if (node >= N_NODES) return;
    int col = lane * 4;
    float4 m;
    acc_range(xa, g_srcs[0], g_off[0][node], g_off[0][node + 1], col, m);
    float4 xd = *(const float4*)(xb + (size_t)node * NC + col);
    m.x += xd.x; m.y += xd.y; m.z += xd.z; m.w += xd.w;
    *(float4*)(mid + (size_t)node * NC + col) = m;
}

// ba (src=x_b) + aa (src=x_a) edges, dst=x_a -> mid_a [N,256]
__global__ void agg_a_kernel(const float* __restrict__ xa, const float* __restrict__ xb,
                             float* __restrict__ mid) {
    int g = blockIdx.x * blockDim.x + threadIdx.x;
    int node = g >> 5, lane = g & 31;
    if (node >= N_NODES) return;
    int col = lane * 4;
    float4 xd = *(const float4*)(xa + (size_t)node * NC + col);
    float4 m0, m1;
    acc_range(xb, g_srcs[1], g_off[1][node], g_off[1][node + 1], col, m0);
    acc_range(xa, g_srcs[2], g_off[2][node], g_off[2][node + 1], col, m1);
    m0.x += xd.x; m0.y += xd.y; m0.z += xd.z; m0.w += xd.w;
    m1.x += xd.x; m1.y += xd.y; m1.z += xd.z; m1.w += xd.w;
    *(float4*)(mid + (size_t)node * 256 + col) = m0;
    *(float4*)(mid + (size_t)node * 256 + 128 + col) = m1;
}

// ---------------- tf32 GEMM + bias + LayerNorm + ReLU fused ----------------
__device__ __forceinline__ float tf32r(float x) {
    unsigned u;
    asm("cvt.rna.tf32.f32 %0, %1;" : "=r"(u) : "f"(x));
    return __uint_as_float(u);
}

#define APITCH 36
#define OPITCH 132

template <int K>
__global__ void __launch_bounds__(256, 2)
gemm_ln_kernel(const float* __restrict__ A, const float* __restrict__ W,
               const float* __restrict__ b1, const float* __restrict__ b2,
               const float* __restrict__ lw, const float* __restrict__ lb,
               float* __restrict__ out, int M) {
    extern __shared__ float buf[];           // max(2*128*36, 128*132) = 16896 floats
    float* At = buf;                         // [128][36]
    float* Wt = buf + 128 * APITCH;
    __shared__ float sb[3][NC];

    int tid = threadIdx.x;
    int lane = tid & 31, wid = tid >> 5;
    int warp_m = wid >> 2, warp_n = wid & 3; // 2 x 4 warps
    int gid = lane >> 2, tig = lane & 3;
    int row0 = blockIdx.x * 128;

    if (tid < NC) {
        float c = b1[tid];
        if (b2) c += b2[tid];
        sb[0][tid] = c;
        sb[1][tid] = lw[tid];
        sb[2][tid] = lb[tid];
    }

    float acc[4][4][4];
#pragma unroll
    for (int i = 0; i < 4; i++)
#pragma unroll
        for (int j = 0; j < 4; j++)
#pragma unroll
            for (int c = 0; c < 4; c++) acc[i][j][c] = 0.f;

    for (int kc = 0; kc < K; kc += 32) {
#pragma unroll
        for (int it = 0; it < 4; it++) {
            int idx = tid + it * 256;        // 0..1023
            int r = idx >> 3, seg = idx & 7;
            float4 v = make_float4(0, 0, 0, 0);
            if (row0 + r < M)
                v = *(const float4*)(A + (size_t)(row0 + r) * K + kc + seg * 4);
            float* dp = At + r * APITCH + seg * 4;
            dp[0] = tf32r(v.x); dp[1] = tf32r(v.y); dp[2] = tf32r(v.z); dp[3] = tf32r(v.w);
            float4 w4 = *(const float4*)(W + (size_t)r * K + kc + seg * 4);
            float* dw = Wt + r * APITCH + seg * 4;
            dw[0] = tf32r(w4.x); dw[1] = tf32r(w4.y); dw[2] = tf32r(w4.z); dw[3] = tf32r(w4.w);
        }
        __syncthreads();
#pragma unroll
        for (int ks = 0; ks < 4; ks++) {
            int k = ks * 8;
            unsigned bfr[4][2];
#pragma unroll
            for (int j = 0; j < 4; j++) {
                int n0 = warp_n * 32 + j * 8;
                bfr[j][0] = __float_as_uint(Wt[(n0 + gid) * APITCH + k + tig]);
                bfr[j][1] = __float_as_uint(Wt[(n0 + gid) * APITCH + k + tig + 4]);
            }
#pragma unroll
            for (int i = 0; i < 4; i++) {
                int m0 = warp_m * 64 + i * 16;
                unsigned a0 = __float_as_uint(At[(m0 + gid) * APITCH + k + tig]);
                unsigned a1 = __float_as_uint(At[(m0 + gid + 8) * APITCH + k + tig]);
                unsigned a2 = __float_as_uint(At[(m0 + gid) * APITCH + k + tig + 4]);
                unsigned a3 = __float_as_uint(At[(m0 + gid + 8) * APITCH + k + tig + 4]);
#pragma unroll
                for (int j = 0; j < 4; j++) {
                    asm volatile(
                        "mma.sync.aligned.m16n8k8.row.col.f32.tf32.tf32.f32 "
                        "{%0,%1,%2,%3}, {%4,%5,%6,%7}, {%8,%9}, {%0,%1,%2,%3};\n"
                        : "+f"(acc[i][j][0]), "+f"(acc[i][j][1]),
                          "+f"(acc[i][j][2]), "+f"(acc[i][j][3])
                        : "r"(a0), "r"(a1), "r"(a2), "r"(a3),
                          "r"(bfr[j][0]), "r"(bfr[j][1]));
                }
            }
        }
        __syncthreads();
    }

    float* Ot = buf;                         // [128][132] aliases At/Wt
#pragma unroll
    for (int i = 0; i < 4; i++) {
        int m0 = warp_m * 64 + i * 16;
#pragma unroll
        for (int j = 0; j < 4; j++) {
            int n0 = warp_n * 32 + j * 8 + 2 * tig;
            Ot[(m0 + gid) * OPITCH + n0]         = acc[i][j][0];
            Ot[(m0 + gid) * OPITCH + n0 + 1]     = acc[i][j][1];
            Ot[(m0 + gid + 8) * OPITCH + n0]     = acc[i][j][2];
            Ot[(m0 + gid + 8) * OPITCH + n0 + 1] = acc[i][j][3];
        }
    }
    __syncthreads();

    int col = lane * 4;
    for (int rr = 0; rr < 16; rr++) {
        int r = wid * 16 + rr;
        int grow = row0 + r;
        if (grow >= M) break;
        float4 v = *(const float4*)&Ot[r * OPITCH + col];
        v.x += sb[0][col];     v.y += sb[0][col + 1];
        v.z += sb[0][col + 2]; v.w += sb[0][col + 3];
        float s = v.x + v.y + v.z + v.w;
#pragma unroll
        for (int o = 16; o > 0; o >>= 1) s += __shfl_xor_sync(0xffffffffu, s, o);
        float mu = s * (1.0f / NC);
        float dx = v.x - mu, dy = v.y - mu, dz = v.z - mu, dw = v.w - mu;
        float q = dx * dx + dy * dy + dz * dz + dw * dw;
#pragma unroll
        for (int o = 16; o > 0; o >>= 1) q += __shfl_xor_sync(0xffffffffu, q, o);
        float rs = rsqrtf(q * (1.0f / NC) + LN_EPS);
        float4 y;
        y.x = fmaxf(dx * rs * sb[1][col]     + sb[2][col],     0.f);
        y.y = fmaxf(dy * rs * sb[1][col + 1] + sb[2][col + 1], 0.f);
        y.z = fmaxf(dz * rs * sb[1][col + 2] + sb[2][col + 2], 0.f);
        y.w = fmaxf(dw * rs * sb[1][col + 3] + sb[2][col + 3], 0.f);
        *(float4*)(out + (size_t)grow * NC + col) = y;
    }
}

// ---------------- launch ----------------
extern "C" void kernel_launch(void* const* d_in, const int* in_sizes, int n_in,
                              void* d_out, int out_size) {
    (void)in_sizes; (void)n_in; (void)out_size;
    const float* x_a      = (const float*)d_in[0];
    const float* x_b      = (const float*)d_in[1];
    const float* schema_x = (const float*)d_in[2];
    const int*   e_ab     = (const int*)d_in[3];
    const int*   e_ba     = (const int*)d_in[4];
    const int*   e_aa     = (const int*)d_in[5];
    const int*   sei      = (const int*)d_in[6];
    const float* pre_W    = (const float*)d_in[7];
    const float* pre_b    = (const float*)d_in[8];
    const float* gcn_W    = (const float*)d_in[9];
    const float* gcn_b    = (const float*)d_in[10];
    const float* coeff_W  = (const float*)d_in[11];
    const float* coeff_b  = (const float*)d_in[12];
    const float* bases    = (const float*)d_in[13];
    const float* sage_bias= (const float*)d_in[14];
    const float* ln_w     = (const float*)d_in[15];
    const float* ln_b     = (const float*)d_in[16];

    float* out = (float*)d_out;
    float* out_xa  = out;
    float* out_xb  = out + (size_t)N_NODES * NC;
    float* out_sf  = out + (size_t)2 * N_NODES * NC;
    float* out_ori = out_sf + NS * NH;

    float *p_mid_a, *p_mid_b, *p_xa, *p_xb, *p_Wab, *p_Wcat;
    int* p_pos;
    cudaGetSymbolAddress((void**)&p_mid_a, g_mid_a);
    cudaGetSymbolAddress((void**)&p_mid_b, g_mid_b);
    cudaGetSymbolAddress((void**)&p_xa,    g_xa);
    cudaGetSymbolAddress((void**)&p_xb,    g_xb);
    cudaGetSymbolAddress((void**)&p_Wab,   g_Wab);
    cudaGetSymbolAddress((void**)&p_Wcat,  g_Wcat);
    cudaGetSymbolAddress((void**)&p_pos,   g_pos);

    const int SMEM_GEMM = 16896 * sizeof(float);
    cudaFuncSetAttribute(gemm_ln_kernel<256>,
                         cudaFuncAttributeMaxDynamicSharedMemorySize, SMEM_GEMM);
    cudaFuncSetAttribute(gemm_ln_kernel<128>,
                         cudaFuncAttributeMaxDynamicSharedMemorySize, SMEM_GEMM);

    // ---- CSR build ----
    cudaMemsetAsync(p_pos, 0, sizeof(int) * 3 * N_NODES);
    hist3_kernel<<<3 * NE / 256, 256>>>(e_ab, e_ba, e_aa);
    scan1_kernel<<<3 * SCAN_NB, 1024>>>();
    scan2_kernel<<<1, 32>>>();
    scan3_kernel<<<3 * SCAN_NB, 1024>>>();
    fill3_kernel<<<3 * NE / 256, 256>>>(e_ab, e_ba, e_aa);

    // ---- schema + dynamic weights ----
    schema_kernel<<<1, 512>>>(schema_x, sei, pre_W, pre_b, gcn_W, gcn_b,
                              coeff_W, coeff_b, out_sf, out_ori);
    buildW_kernel<<<(2 * NC * NC + 255) / 256, 256>>>(bases);

    const int AGG_GRID  = (N_NODES * 32 + 255) / 256;
    const int GEMM_GRID = (N_NODES + 127) / 128;

    // ---- layer 0 ----
    agg_b_kernel<<<AGG_GRID, 256>>>(x_a, x_b, p_mid_b);
    agg_a_kernel<<<AGG_GRID, 256>>>(x_a, x_b, p_mid_a);
    gemm_ln_kernel<256><<<GEMM_GRID, 256, SMEM_GEMM>>>(
        p_mid_a, p_Wcat, sage_bias + 1 * NC, sage_bias + 2 * NC,
        ln_w + 0 * NC, ln_b + 0 * NC, p_xa, N_NODES);
    gemm_ln_kernel<128><<<GEMM_GRID, 256, SMEM_GEMM>>>(
        p_mid_b, p_Wab, sage_bias + 0 * NC, nullptr,
        ln_w + 1 * NC, ln_b + 1 * NC, p_xb, N_NODES);

    // ---- layer 1 ----
    agg_b_kernel<<<AGG_GRID, 256>>>(p_xa, p_xb, p_mid_b);
    agg_a_kernel<<<AGG_GRID, 256>>>(p_xa, p_xb, p_mid_a);
    gemm_ln_kernel<256><<<GEMM_GRID, 256, SMEM_GEMM>>>(
        p_mid_a, p_Wcat + NC * 256, sage_bias + 4 * NC, sage_bias + 5 * NC,
        ln_w + 2 * NC, ln_b + 2 * NC, out_xa, N_NODES);
    gemm_ln_kernel<128><<<GEMM_GRID, 256, SMEM_GEMM>>>(
        p_mid_b, p_Wab + NC * NC, sage_bias + 3 * NC, nullptr,
        ln_w + 3 * NC, ln_b + 3 * NC, out_xb, N_NODES);
}

// round 7
// speedup vs baseline: 1.3978x; 1.3925x over previous
#include <cuda_runtime.h>
#include <cstddef>

#define N_NODES 50000
#define NC 128
#define NE 800000
#define NS 8
#define NH 64
#define NB_ 8
#define LN_EPS 1e-5f
#define SCAN_NB 13
#define SCAN_CHUNK 4096

// ---------------- scratch (device globals; no allocation) ----------------
__device__ int   g_off [3][N_NODES + 1];
__device__ int   g_pos [3][N_NODES];       // degree hist -> write cursors
__device__ int   g_bsum[3][SCAN_NB];
__device__ int   g_srcs[3][NE];
__device__ float g_mid_a[(size_t)N_NODES * 256];
__device__ float g_mid_b[(size_t)N_NODES * NC];
__device__ float g_xa   [(size_t)N_NODES * NC];
__device__ float g_xb   [(size_t)N_NODES * NC];
__device__ float g_Wab [2][NC * NC];
__device__ float g_Wcat[2][NC * 256];      // [j][0:128]=W_ba  [j][128:256]=W_aa
__device__ float g_coeff[3][NB_];          // 0: ab, 1: ba, 2: aa

// ---------------- CSR build ----------------
__global__ void hist3_kernel(const int* __restrict__ e0, const int* __restrict__ e1,
                             const int* __restrict__ e2) {
    int i = blockIdx.x * blockDim.x + threadIdx.x;  // grid covers exactly 3*NE
    int t = i / NE, j = i % NE;
    const int* e = (t == 0) ? e0 : (t == 1) ? e1 : e2;
    atomicAdd(&g_pos[t][e[NE + j]], 1);
}

__global__ void scan1_kernel() {           // grid = 3*SCAN_NB, block = 1024
    int t = blockIdx.x / SCAN_NB, c = blockIdx.x % SCAN_NB;
    int base = c * SCAN_CHUNK;
    int tid = threadIdx.x;
    int v = 0;
#pragma unroll
    for (int i = 0; i < 4; i++) {
        int idx = base + tid * 4 + i;
        if (idx < N_NODES) v += g_pos[t][idx];
    }
#pragma unroll
    for (int o = 16; o > 0; o >>= 1) v += __shfl_xor_sync(0xffffffffu, v, o);
    __shared__ int ws[32];
    if ((tid & 31) == 0) ws[tid >> 5] = v;
    __syncthreads();
    if (tid < 32) {
        int s = ws[tid];
#pragma unroll
        for (int o = 16; o > 0; o >>= 1) s += __shfl_xor_sync(0xffffffffu, s, o);
        if (tid == 0) g_bsum[t][c] = s;
    }
}

__global__ void scan2_kernel() {
    if (threadIdx.x == 0) {
        for (int t = 0; t < 3; t++) {
            int run = 0;
            for (int c = 0; c < SCAN_NB; c++) {
                int v = g_bsum[t][c];
                g_bsum[t][c] = run;
                run += v;
            }
            g_off[t][N_NODES] = run;
        }
    }
}

__global__ void scan3_kernel() {           // grid = 3*SCAN_NB, block = 1024
    int t = blockIdx.x / SCAN_NB, c = blockIdx.x % SCAN_NB;
    int base = c * SCAN_CHUNK;
    int tid = threadIdx.x, lane = tid & 31, wid = tid >> 5;
    int v[4], s = 0;
#pragma unroll
    for (int i = 0; i < 4; i++) {
        int idx = base + tid * 4 + i;
        v[i] = (idx < N_NODES) ? g_pos[t][idx] : 0;
        s += v[i];
    }
    int si = s;
#pragma unroll
    for (int d = 1; d < 32; d <<= 1) {
        int n = __shfl_up_sync(0xffffffffu, si, d);
        if (lane >= d) si += n;
    }
    __shared__ int ws[32];
    if (lane == 31) ws[wid] = si;
    __syncthreads();
    if (wid == 0) {
        int w = ws[lane];
#pragma unroll
        for (int d = 1; d < 32; d <<= 1) {
            int n = __shfl_up_sync(0xffffffffu, w, d);
            if (lane >= d) w += n;
        }
        ws[lane] = w;
    }
    __syncthreads();
    int run = si - s + (wid ? ws[wid - 1] : 0) + g_bsum[t][c];
#pragma unroll
    for (int i = 0; i < 4; i++) {
        int idx = base + tid * 4 + i;
        if (idx < N_NODES) {
            g_off[t][idx] = run;
            g_pos[t][idx] = run;
            run += v[i];
        }
    }
}

__global__ void fill3_kernel(const int* __restrict__ e0, const int* __restrict__ e1,
                             const int* __restrict__ e2) {
    int i = blockIdx.x * blockDim.x + threadIdx.x;
    int t = i / NE, j = i % NE;
    const int* e = (t == 0) ? e0 : (t == 1) ? e1 : e2;
    int s = e[j], d = e[NE + j];
    int p = atomicAdd(&g_pos[t][d], 1);
    g_srcs[t][p] = s;
}

// ---------------- schema GCN + dynamic coefficients (1 block, 512 thr) ----------------
__global__ void schema_kernel(const float* __restrict__ schema_x, const int* __restrict__ sei,
                              const float* __restrict__ pre_W, const float* __restrict__ pre_b,
                              const float* __restrict__ gcn_W, const float* __restrict__ gcn_b,
                              const float* __restrict__ coeff_W, const float* __restrict__ coeff_b,
                              float* __restrict__ out_sf, float* __restrict__ out_ori) {
    __shared__ float h [NS][NH];
    __shared__ float xw[NS][NH];
    __shared__ float sf[NS][NH];
    __shared__ float dinv[NS];
    int tid = threadIdx.x;              // 512 = 8*64
    int s = tid / NH, j = tid % NH;

    float acc = pre_b[j];
    for (int i = 0; i < NH; i++) acc += schema_x[s * NH + i] * pre_W[j * NH + i];
    h[s][j] = acc;
    out_ori[s * NH + j] = acc;
    __syncthreads();

    float xacc = 0.f;
    for (int k = 0; k < NH; k++) xacc += h[s][k] * gcn_W[j * NH + k];
    xw[s][j] = xacc;
    if (tid < NS) {
        float d = 1.0f;
        for (int e = 0; e < 24; e++) if (sei[24 + e] == tid) d += 1.0f;
        dinv[tid] = rsqrtf(fmaxf(d, 1e-12f));
    }
    __syncthreads();

    float o = gcn_b[j] + dinv[s] * dinv[s] * xw[s][j];
    for (int e = 0; e < 24; e++) {
        int es = sei[e], ed = sei[24 + e];
        if (ed == s) o += dinv[es] * dinv[s] * xw[es][j];
    }
    o = fmaxf(o, 0.f);
    sf[s][j] = o;
    out_sf[s * NH + j] = o;
    __syncthreads();

    if (tid < 3 * NB_) {
        int t = tid / NB_, i = tid % NB_;
        int ssrc = (t == 1) ? 1 : 0;
        int sdst = (t == 0) ? 1 : 0;
        float c = coeff_b[i];
        for (int k = 0; k < NH; k++) c += sf[ssrc][k] * coeff_W[i * 128 + k];
        for (int k = 0; k < NH; k++) c += sf[sdst][k] * coeff_W[i * 128 + 64 + k];
        g_coeff[t][i] = c;
    }
}

__global__ void buildW_kernel(const float* __restrict__ bases) {
    int id = blockIdx.x * blockDim.x + threadIdx.x;
    if (id >= 2 * NC * NC) return;
    int l = id / (NC * NC);
    int jk = id % (NC * NC);
    int j = jk / NC, k = jk % NC;
    float wab = 0.f, wba = 0.f, waa = 0.f;
#pragma unroll
    for (int i = 0; i < NB_; i++) {
        float b = bases[(size_t)l * NB_ * NC * NC + (size_t)i * NC * NC + jk];
        wab += g_coeff[0][i] * b;
        wba += g_coeff[1][i] * b;
        waa += g_coeff[2][i] * b;
    }
    g_Wab[l][jk] = wab;
    g_Wcat[l][j * 256 + k] = wba;
    g_Wcat[l][j * 256 + 128 + k] = waa;
}

// ---------------- aggregation: warp per destination node, MLP=4 ----------------
__device__ __forceinline__ void acc_range(const float* __restrict__ xsrc,
                                          const int* __restrict__ srcs,
                                          int beg, int end, int col, float4& out) {
    float4 a0 = make_float4(0, 0, 0, 0), a1 = a0, a2 = a0, a3 = a0;
    int e = beg;
    for (; e + 4 <= end; e += 4) {
        int s0 = srcs[e], s1 = srcs[e + 1], s2 = srcs[e + 2], s3 = srcs[e + 3];
        float4 v0 = *(const float4*)(xsrc + (size_t)s0 * NC + col);
        float4 v1 = *(const float4*)(xsrc + (size_t)s1 * NC + col);
        float4 v2 = *(const float4*)(xsrc + (size_t)s2 * NC + col);
        float4 v3 = *(const float4*)(xsrc + (size_t)s3 * NC + col);
        a0.x += v0.x; a0.y += v0.y; a0.z += v0.z; a0.w += v0.w;
        a1.x += v1.x; a1.y += v1.y; a1.z += v1.z; a1.w += v1.w;
        a2.x += v2.x; a2.y += v2.y; a2.z += v2.z; a2.w += v2.w;
        a3.x += v3.x; a3.y += v3.y; a3.z += v3.z; a3.w += v3.w;
    }
    for (; e < end; e++) {
        int s0 = srcs[e];
        float4 v0 = *(const float4*)(xsrc + (size_t)s0 * NC + col);
        a0.x += v0.x; a0.y += v0.y; a0.z += v0.z; a0.w += v0.w;
    }
    float inv = 1.0f / fmaxf((float)(end - beg), 1.0f);
    out.x = (a0.x + a1.x + a2.x + a3.x) * inv;
    out.y = (a0.y + a1.y + a2.y + a3.y) * inv;
    out.z = (a0.z + a1.z + a2.z + a3.z) * inv;
    out.w = (a0.w + a1.w + a2.w + a3.w) * inv;
}

// ab edges: src=x_a, dst=x_b -> mid_b [N,128]
__global__ void agg_b_kernel(const float* __restrict__ xa, const float* __restrict__ xb,
                             float* __restrict__ mid) {
    int g = blockIdx.x * blockDim.x + threadIdx.x;
    int node = g >> 5, lane = g & 31;
    if (node >= N_NODES) return;
    int col = lane * 4;
    float4 m;
    acc_range(xa, g_srcs[0], g_off[0][node], g_off[0][node + 1], col, m);
    float4 xd = *(const float4*)(xb + (size_t)node * NC + col);
    m.x += xd.x; m.y += xd.y; m.z += xd.z; m.w += xd.w;
    *(float4*)(mid + (size_t)node * NC + col) = m;
}

// ba (src=x_b) + aa (src=x_a) edges, dst=x_a -> mid_a [N,256]
__global__ void agg_a_kernel(const float* __restrict__ xa, const float* __restrict__ xb,
                             float* __restrict__ mid) {
    int g = blockIdx.x * blockDim.x + threadIdx.x;
    int node = g >> 5, lane = g & 31;
    if (node >= N_NODES) return;
    int col = lane * 4;
    float4 xd = *(const float4*)(xa + (size_t)node * NC + col);
    float4 m0, m1;
    acc_range(xb, g_srcs[1], g_off[1][node], g_off[1][node + 1], col, m0);
    acc_range(xa, g_srcs[2], g_off[2][node], g_off[2][node + 1], col, m1);
    m0.x += xd.x; m0.y += xd.y; m0.z += xd.z; m0.w += xd.w;
    m1.x += xd.x; m1.y += xd.y; m1.z += xd.z; m1.w += xd.w;
    *(float4*)(mid + (size_t)node * 256 + col) = m0;
    *(float4*)(mid + (size_t)node * 256 + 128 + col) = m1;
}

// ---------------- tf32 GEMM + bias + LayerNorm + ReLU fused ----------------
__device__ __forceinline__ float tf32r(float x) {
    unsigned u;
    asm("cvt.rna.tf32.f32 %0, %1;" : "=r"(u) : "f"(x));
    return __uint_as_float(u);
}

#define APITCH 36
#define OPITCH 132

template <int K>
__global__ void __launch_bounds__(256)
gemm_ln_kernel(const float* __restrict__ A, const float* __restrict__ W,
               const float* __restrict__ b1, const float* __restrict__ b2,
               const float* __restrict__ lw, const float* __restrict__ lb,
               float* __restrict__ out, int M) {
    extern __shared__ float buf[];           // max(2*128*36, 128*132) = 16896 floats
    float* At = buf;                         // [128][36]
    float* Wt = buf + 128 * APITCH;
    __shared__ float sb[3][NC];

    int tid = threadIdx.x;
    int lane = tid & 31, wid = tid >> 5;
    int warp_m = wid >> 2, warp_n = wid & 3; // 2 x 4 warps
    int gid = lane >> 2, tig = lane & 3;
    int row0 = blockIdx.x * 128;

    if (tid < NC) {
        float c = b1[tid];
        if (b2) c += b2[tid];
        sb[0][tid] = c;
        sb[1][tid] = lw[tid];
        sb[2][tid] = lb[tid];
    }

    float acc[4][4][4];
#pragma unroll
    for (int i = 0; i < 4; i++)
#pragma unroll
        for (int j = 0; j < 4; j++)
#pragma unroll
            for (int c = 0; c < 4; c++) acc[i][j][c] = 0.f;

    for (int kc = 0; kc < K; kc += 32) {
#pragma unroll
        for (int it = 0; it < 4; it++) {
            int idx = tid + it * 256;        // 0..1023
            int r = idx >> 3, seg = idx & 7;
            float4 v = make_float4(0, 0, 0, 0);
            if (row0 + r < M)
                v = *(const float4*)(A + (size_t)(row0 + r) * K + kc + seg * 4);
            float* dp = At + r * APITCH + seg * 4;
            dp[0] = tf32r(v.x); dp[1] = tf32r(v.y); dp[2] = tf32r(v.z); dp[3] = tf32r(v.w);
            float4 w4 = *(const float4*)(W + (size_t)r * K + kc + seg * 4);
            float* dw = Wt + r * APITCH + seg * 4;
            dw[0] = tf32r(w4.x); dw[1] = tf32r(w4.y); dw[2] = tf32r(w4.z); dw[3] = tf32r(w4.w);
        }
        __syncthreads();
#pragma unroll
        for (int ks = 0; ks < 4; ks++) {
            int k = ks * 8;
            unsigned bfr[4][2];
#pragma unroll
            for (int j = 0; j < 4; j++) {
                int n0 = warp_n * 32 + j * 8;
                bfr[j][0] = __float_as_uint(Wt[(n0 + gid) * APITCH + k + tig]);
                bfr[j][1] = __float_as_uint(Wt[(n0 + gid) * APITCH + k + tig + 4]);
            }
#pragma unroll
            for (int i = 0; i < 4; i++) {
                int m0 = warp_m * 64 + i * 16;
                unsigned a0 = __float_as_uint(At[(m0 + gid) * APITCH + k + tig]);
                unsigned a1 = __float_as_uint(At[(m0 + gid + 8) * APITCH + k + tig]);
                unsigned a2 = __float_as_uint(At[(m0 + gid) * APITCH + k + tig + 4]);
                unsigned a3 = __float_as_uint(At[(m0 + gid + 8) * APITCH + k + tig + 4]);
#pragma unroll
                for (int j = 0; j < 4; j++) {
                    asm volatile(
                        "mma.sync.aligned.m16n8k8.row.col.f32.tf32.tf32.f32 "
                        "{%0,%1,%2,%3}, {%4,%5,%6,%7}, {%8,%9}, {%0,%1,%2,%3};\n"
                        : "+f"(acc[i][j][0]), "+f"(acc[i][j][1]),
                          "+f"(acc[i][j][2]), "+f"(acc[i][j][3])
                        : "r"(a0), "r"(a1), "r"(a2), "r"(a3),
                          "r"(bfr[j][0]), "r"(bfr[j][1]));
                }
            }
        }
        __syncthreads();
    }

    float* Ot = buf;                         // [128][132] aliases At/Wt
#pragma unroll
    for (int i = 0; i < 4; i++) {
        int m0 = warp_m * 64 + i * 16;
#pragma unroll
        for (int j = 0; j < 4; j++) {
            int n0 = warp_n * 32 + j * 8 + 2 * tig;
            Ot[(m0 + gid) * OPITCH + n0]         = acc[i][j][0];
            Ot[(m0 + gid) * OPITCH + n0 + 1]     = acc[i][j][1];
            Ot[(m0 + gid + 8) * OPITCH + n0]     = acc[i][j][2];
            Ot[(m0 + gid + 8) * OPITCH + n0 + 1] = acc[i][j][3];
        }
    }
    __syncthreads();

    int col = lane * 4;
    for (int rr = 0; rr < 16; rr++) {
        int r = wid * 16 + rr;
        int grow = row0 + r;
        if (grow >= M) break;
        float4 v = *(const float4*)&Ot[r * OPITCH + col];
        v.x += sb[0][col];     v.y += sb[0][col + 1];
        v.z += sb[0][col + 2]; v.w += sb[0][col + 3];
        float s = v.x + v.y + v.z + v.w;
#pragma unroll
        for (int o = 16; o > 0; o >>= 1) s += __shfl_xor_sync(0xffffffffu, s, o);
        float mu = s * (1.0f / NC);
        float dx = v.x - mu, dy = v.y - mu, dz = v.z - mu, dw = v.w - mu;
        float q = dx * dx + dy * dy + dz * dz + dw * dw;
#pragma unroll
        for (int o = 16; o > 0; o >>= 1) q += __shfl_xor_sync(0xffffffffu, q, o);
        float rs = rsqrtf(q * (1.0f / NC) + LN_EPS);
        float4 y;
        y.x = fmaxf(dx * rs * sb[1][col]     + sb[2][col],     0.f);
        y.y = fmaxf(dy * rs * sb[1][col + 1] + sb[2][col + 1], 0.f);
        y.z = fmaxf(dz * rs * sb[1][col + 2] + sb[2][col + 2], 0.f);
        y.w = fmaxf(dw * rs * sb[1][col + 3] + sb[2][col + 3], 0.f);
        *(float4*)(out + (size_t)grow * NC + col) = y;
    }
}

// ---------------- launch ----------------
extern "C" void kernel_launch(void* const* d_in, const int* in_sizes, int n_in,
                              void* d_out, int out_size) {
    (void)in_sizes; (void)n_in; (void)out_size;
    const float* x_a      = (const float*)d_in[0];
    const float* x_b      = (const float*)d_in[1];
    const float* schema_x = (const float*)d_in[2];
    const int*   e_ab     = (const int*)d_in[3];
    const int*   e_ba     = (const int*)d_in[4];
    const int*   e_aa     = (const int*)d_in[5];
    const int*   sei      = (const int*)d_in[6];
    const float* pre_W    = (const float*)d_in[7];
    const float* pre_b    = (const float*)d_in[8];
    const float* gcn_W    = (const float*)d_in[9];
    const float* gcn_b    = (const float*)d_in[10];
    const float* coeff_W  = (const float*)d_in[11];
    const float* coeff_b  = (const float*)d_in[12];
    const float* bases    = (const float*)d_in[13];
    const float* sage_bias= (const float*)d_in[14];
    const float* ln_w     = (const float*)d_in[15];
    const float* ln_b     = (const float*)d_in[16];

    float* out = (float*)d_out;
    float* out_xa  = out;
    float* out_xb  = out + (size_t)N_NODES * NC;
    float* out_sf  = out + (size_t)2 * N_NODES * NC;
    float* out_ori = out_sf + NS * NH;

    float *p_mid_a, *p_mid_b, *p_xa, *p_xb, *p_Wab, *p_Wcat;
    int* p_pos;
    cudaGetSymbolAddress((void**)&p_mid_a, g_mid_a);
    cudaGetSymbolAddress((void**)&p_mid_b, g_mid_b);
    cudaGetSymbolAddress((void**)&p_xa,    g_xa);
    cudaGetSymbolAddress((void**)&p_xb,    g_xb);
    cudaGetSymbolAddress((void**)&p_Wab,   g_Wab);
    cudaGetSymbolAddress((void**)&p_Wcat,  g_Wcat);
    cudaGetSymbolAddress((void**)&p_pos,   g_pos);

    const int SMEM_GEMM = 16896 * sizeof(float);
    cudaFuncSetAttribute(gemm_ln_kernel<256>,
                         cudaFuncAttributeMaxDynamicSharedMemorySize, SMEM_GEMM);
    cudaFuncSetAttribute(gemm_ln_kernel<128>,
                         cudaFuncAttributeMaxDynamicSharedMemorySize, SMEM_GEMM);

    // ---- CSR build ----
    cudaMemsetAsync(p_pos, 0, sizeof(int) * 3 * N_NODES);
    hist3_kernel<<<3 * NE / 256, 256>>>(e_ab, e_ba, e_aa);
    scan1_kernel<<<3 * SCAN_NB, 1024>>>();
    scan2_kernel<<<1, 32>>>();
    scan3_kernel<<<3 * SCAN_NB, 1024>>>();
    fill3_kernel<<<3 * NE / 256, 256>>>(e_ab, e_ba, e_aa);

    // ---- schema + dynamic weights ----
    schema_kernel<<<1, 512>>>(schema_x, sei, pre_W, pre_b, gcn_W, gcn_b,
                              coeff_W, coeff_b, out_sf, out_ori);
    buildW_kernel<<<(2 * NC * NC + 255) / 256, 256>>>(bases);

    const int AGG_GRID  = (N_NODES * 32 + 255) / 256;
    const int GEMM_GRID = (N_NODES + 127) / 128;

    // ---- layer 0 ----
    agg_b_kernel<<<AGG_GRID, 256>>>(x_a, x_b, p_mid_b);
    agg_a_kernel<<<AGG_GRID, 256>>>(x_a, x_b, p_mid_a);
    gemm_ln_kernel<256><<<GEMM_GRID, 256, SMEM_GEMM>>>(
        p_mid_a, p_Wcat, sage_bias + 1 * NC, sage_bias + 2 * NC,
        ln_w + 0 * NC, ln_b + 0 * NC, p_xa, N_NODES);
    gemm_ln_kernel<128><<<GEMM_GRID, 256, SMEM_GEMM>>>(
        p_mid_b, p_Wab, sage_bias + 0 * NC, nullptr,
        ln_w + 1 * NC, ln_b + 1 * NC, p_xb, N_NODES);

    // ---- layer 1 ----
    agg_b_kernel<<<AGG_GRID, 256>>>(p_xa, p_xb, p_mid_b);
    agg_a_kernel<<<AGG_GRID, 256>>>(p_xa, p_xb, p_mid_a);
    gemm_ln_kernel<256><<<GEMM_GRID, 256, SMEM_GEMM>>>(
        p_mid_a, p_Wcat + NC * 256, sage_bias + 4 * NC, sage_bias + 5 * NC,
        ln_w + 2 * NC, ln_b + 2 * NC, out_xa, N_NODES);
    gemm_ln_kernel<128><<<GEMM_GRID, 256, SMEM_GEMM>>>(
        p_mid_b, p_Wab + NC * NC, sage_bias + 3 * NC, nullptr,
        ln_w + 3 * NC, ln_b + 3 * NC, out_xb, N_NODES);
}

// round 8
// speedup vs baseline: 1.4836x; 1.0614x over previous
#include <cuda_runtime.h>
#include <cuda_fp16.h>
#include <cstddef>

#define N_NODES 50000
#define NC 128
#define NE 800000
#define NS 8
#define NH 64
#define NB_ 8
#define LN_EPS 1e-5f
#define SCAN_NB 13
#define SCAN_CHUNK 4096

// ---------------- scratch (device globals; no allocation) ----------------
__device__ int    g_off [3][N_NODES + 1];
__device__ int    g_pos [3][N_NODES];      // degree hist -> write cursors
__device__ int    g_bsum[3][SCAN_NB];
__device__ int    g_srcs[3][NE];
__device__ float  g_mid_a[(size_t)N_NODES * 256];
__device__ float  g_mid_b[(size_t)N_NODES * NC];
__device__ __half g_ha[(size_t)N_NODES * NC];
__device__ __half g_hb[(size_t)N_NODES * NC];
__device__ float  g_Wab [2][NC * NC];
__device__ float  g_Wcat[2][NC * 256];     // [j][0:128]=W_ba  [j][128:256]=W_aa
__device__ float  g_coeff[3][NB_];         // 0: ab, 1: ba, 2: aa

// ---------------- CSR build ----------------
__global__ void hist3_kernel(const int* __restrict__ e0, const int* __restrict__ e1,
                             const int* __restrict__ e2) {
    int i = blockIdx.x * blockDim.x + threadIdx.x;  // grid covers exactly 3*NE
    int t = i / NE, j = i % NE;
    const int* e = (t == 0) ? e0 : (t == 1) ? e1 : e2;
    atomicAdd(&g_pos[t][e[NE + j]], 1);
}

__global__ void scan1_kernel() {           // grid = 3*SCAN_NB, block = 1024
    int t = blockIdx.x / SCAN_NB, c = blockIdx.x % SCAN_NB;
    int base = c * SCAN_CHUNK;
    int tid = threadIdx.x;
    int v = 0;
#pragma unroll
    for (int i = 0; i < 4; i++) {
        int idx = base + tid * 4 + i;
        if (idx < N_NODES) v += g_pos[t][idx];
    }
#pragma unroll
    for (int o = 16; o > 0; o >>= 1) v += __shfl_xor_sync(0xffffffffu, v, o);
    __shared__ int ws[32];
    if ((tid & 31) == 0) ws[tid >> 5] = v;
    __syncthreads();
    if (tid < 32) {
        int s = ws[tid];
#pragma unroll
        for (int o = 16; o > 0; o >>= 1) s += __shfl_xor_sync(0xffffffffu, s, o);
        if (tid == 0) g_bsum[t][c] = s;
    }
}

__global__ void scan2_kernel() {
    if (threadIdx.x == 0) {
        for (int t = 0; t < 3; t++) {
            int run = 0;
            for (int c = 0; c < SCAN_NB; c++) {
                int v = g_bsum[t][c];
                g_bsum[t][c] = run;
                run += v;
            }
            g_off[t][N_NODES] = run;
        }
    }
}

__global__ void scan3_kernel() {           // grid = 3*SCAN_NB, block = 1024
    int t = blockIdx.x / SCAN_NB, c = blockIdx.x % SCAN_NB;
    int base = c * SCAN_CHUNK;
    int tid = threadIdx.x, lane = tid & 31, wid = tid >> 5;
    int v[4], s = 0;
#pragma unroll
    for (int i = 0; i < 4; i++) {
        int idx = base + tid * 4 + i;
        v[i] = (idx < N_NODES) ? g_pos[t][idx] : 0;
        s += v[i];
    }
    int si = s;
#pragma unroll
    for (int d = 1; d < 32; d <<= 1) {
        int n = __shfl_up_sync(0xffffffffu, si, d);
        if (lane >= d) si += n;
    }
    __shared__ int ws[32];
    if (lane == 31) ws[wid] = si;
    __syncthreads();
    if (wid == 0) {
        int w = ws[lane];
#pragma unroll
        for (int d = 1; d < 32; d <<= 1) {
            int n = __shfl_up_sync(0xffffffffu, w, d);
            if (lane >= d) w += n;
        }
        ws[lane] = w;
    }
    __syncthreads();
    int run = si - s + (wid ? ws[wid - 1] : 0) + g_bsum[t][c];
#pragma unroll
    for (int i = 0; i < 4; i++) {
        int idx = base + tid * 4 + i;
        if (idx < N_NODES) {
            g_off[t][idx] = run;
            g_pos[t][idx] = run;
            run += v[i];
        }
    }
}

__global__ void fill3_kernel(const int* __restrict__ e0, const int* __restrict__ e1,
                             const int* __restrict__ e2) {
    int i = blockIdx.x * blockDim.x + threadIdx.x;
    int t = i / NE, j = i % NE;
    const int* e = (t == 0) ? e0 : (t == 1) ? e1 : e2;
    int s = e[j], d = e[NE + j];
    int p = atomicAdd(&g_pos[t][d], 1);
    g_srcs[t][p] = s;
}

// ---------------- fp16 copies of the input tables ----------------
__device__ __forceinline__ unsigned pack2(float a, float b) {
    __half2 h = __floats2half2_rn(a, b);
    return *(unsigned*)&h;
}

__global__ void tohalf_kernel(const float* __restrict__ xa, const float* __restrict__ xb) {
    int i = blockIdx.x * blockDim.x + threadIdx.x;   // each handles 8 floats
    const size_t TOT = (size_t)N_NODES * NC;
    size_t base = (size_t)i * 8;
    const float* src;
    __half* dst;
    if (base < TOT) { src = xa + base; dst = g_ha + base; }
    else            { src = xb + (base - TOT); dst = g_hb + (base - TOT); }
    float4 v0 = *(const float4*)src;
    float4 v1 = *(const float4*)(src + 4);
    uint4 u = make_uint4(pack2(v0.x, v0.y), pack2(v0.z, v0.w),
                         pack2(v1.x, v1.y), pack2(v1.z, v1.w));
    *(uint4*)dst = u;
}

// ---------------- schema GCN + dynamic coefficients (1 block, 512 thr) ----------------
__global__ void schema_kernel(const float* __restrict__ schema_x, const int* __restrict__ sei,
                              const float* __restrict__ pre_W, const float* __restrict__ pre_b,
                              const float* __restrict__ gcn_W, const float* __restrict__ gcn_b,
                              const float* __restrict__ coeff_W, const float* __restrict__ coeff_b,
                              float* __restrict__ out_sf, float* __restrict__ out_ori) {
    __shared__ float h [NS][NH];
    __shared__ float xw[NS][NH];
    __shared__ float sf[NS][NH];
    __shared__ float dinv[NS];
    int tid = threadIdx.x;              // 512 = 8*64
    int s = tid / NH, j = tid % NH;

    float acc = pre_b[j];
    for (int i = 0; i < NH; i++) acc += schema_x[s * NH + i] * pre_W[j * NH + i];
    h[s][j] = acc;
    out_ori[s * NH + j] = acc;
    __syncthreads();

    float xacc = 0.f;
    for (int k = 0; k < NH; k++) xacc += h[s][k] * gcn_W[j * NH + k];
    xw[s][j] = xacc;
    if (tid < NS) {
        float d = 1.0f;
        for (int e = 0; e < 24; e++) if (sei[24 + e] == tid) d += 1.0f;
        dinv[tid] = rsqrtf(fmaxf(d, 1e-12f));
    }
    __syncthreads();

    float o = gcn_b[j] + dinv[s] * dinv[s] * xw[s][j];
    for (int e = 0; e < 24; e++) {
        int es = sei[e], ed = sei[24 + e];
        if (ed == s) o += dinv[es] * dinv[s] * xw[es][j];
    }
    o = fmaxf(o, 0.f);
    sf[s][j] = o;
    out_sf[s * NH + j] = o;
    __syncthreads();

    if (tid < 3 * NB_) {
        int t = tid / NB_, i = tid % NB_;
        int ssrc = (t == 1) ? 1 : 0;
        int sdst = (t == 0) ? 1 : 0;
        float c = coeff_b[i];
        for (int k = 0; k < NH; k++) c += sf[ssrc][k] * coeff_W[i * 128 + k];
        for (int k = 0; k < NH; k++) c += sf[sdst][k] * coeff_W[i * 128 + 64 + k];
        g_coeff[t][i] = c;
    }
}

__global__ void buildW_kernel(const float* __restrict__ bases) {
    int id = blockIdx.x * blockDim.x + threadIdx.x;
    if (id >= 2 * NC * NC) return;
    int l = id / (NC * NC);
    int jk = id % (NC * NC);
    int j = jk / NC, k = jk % NC;
    float wab = 0.f, wba = 0.f, waa = 0.f;
#pragma unroll
    for (int i = 0; i < NB_; i++) {
        float b = bases[(size_t)l * NB_ * NC * NC + (size_t)i * NC * NC + jk];
        wab += g_coeff[0][i] * b;
        wba += g_coeff[1][i] * b;
        waa += g_coeff[2][i] * b;
    }
    g_Wab[l][jk] = wab;
    g_Wcat[l][j * 256 + k] = wba;
    g_Wcat[l][j * 256 + 128 + k] = waa;
}

// ---------------- aggregation (fp16 sources, fp32 accum, MLP=4) ----------------
__device__ __forceinline__ void add_rowh(const __half* __restrict__ p, float4& a) {
    uint2 u = *(const uint2*)p;
    __half2 h0 = *(__half2*)&u.x, h1 = *(__half2*)&u.y;
    float2 f0 = __half22float2(h0), f1 = __half22float2(h1);
    a.x += f0.x; a.y += f0.y; a.z += f1.x; a.w += f1.y;
}

__device__ __forceinline__ void acc_range(const __half* __restrict__ xsrc,
                                          const int* __restrict__ srcs,
                                          int beg, int end, int col, float4& out) {
    float4 a0 = make_float4(0, 0, 0, 0), a1 = a0, a2 = a0, a3 = a0;
    int e = beg;
    for (; e + 4 <= end; e += 4) {
        int s0 = srcs[e], s1 = srcs[e + 1], s2 = srcs[e + 2], s3 = srcs[e + 3];
        add_rowh(xsrc + (size_t)s0 * NC + col, a0);
        add_rowh(xsrc + (size_t)s1 * NC + col, a1);
        add_rowh(xsrc + (size_t)s2 * NC + col, a2);
        add_rowh(xsrc + (size_t)s3 * NC + col, a3);
    }
    for (; e < end; e++) add_rowh(xsrc + (size_t)srcs[e] * NC + col, a0);
    float inv = 1.0f / fmaxf((float)(end - beg), 1.0f);
    out.x = (a0.x + a1.x + a2.x + a3.x) * inv;
    out.y = (a0.y + a1.y + a2.y + a3.y) * inv;
    out.z = (a0.z + a1.z + a2.z + a3.z) * inv;
    out.w = (a0.w + a1.w + a2.w + a3.w) * inv;
}

// combined: warps [0,N) -> b-dst (ab edges); warps [N,2N) -> a-dst (ba+aa edges)
__global__ void agg_all_kernel(const __half* __restrict__ ha, const __half* __restrict__ hb,
                               float* __restrict__ mid_a, float* __restrict__ mid_b) {
    int g = blockIdx.x * blockDim.x + threadIdx.x;
    int w = g >> 5, lane = g & 31;
    int col = lane * 4;
    if (w < N_NODES) {
        int node = w;
        float4 m;
        acc_range(ha, g_srcs[0], g_off[0][node], g_off[0][node + 1], col, m);
        float4 xd = make_float4(0, 0, 0, 0);
        add_rowh(hb + (size_t)node * NC + col, xd);
        m.x += xd.x; m.y += xd.y; m.z += xd.z; m.w += xd.w;
        *(float4*)(mid_b + (size_t)node * NC + col) = m;
    } else if (w < 2 * N_NODES) {
        int node = w - N_NODES;
        float4 xd = make_float4(0, 0, 0, 0);
        add_rowh(ha + (size_t)node * NC + col, xd);
        float4 m0, m1;
        acc_range(hb, g_srcs[1], g_off[1][node], g_off[1][node + 1], col, m0);
        acc_range(ha, g_srcs[2], g_off[2][node], g_off[2][node + 1], col, m1);
        m0.x += xd.x; m0.y += xd.y; m0.z += xd.z; m0.w += xd.w;
        m1.x += xd.x; m1.y += xd.y; m1.z += xd.z; m1.w += xd.w;
        *(float4*)(mid_a + (size_t)node * 256 + col) = m0;
        *(float4*)(mid_a + (size_t)node * 256 + 128 + col) = m1;
    }
}

// ---------------- tf32 GEMM + bias + LayerNorm + ReLU fused ----------------
__device__ __forceinline__ float tf32r(float x) {
    unsigned u;
    asm("cvt.rna.tf32.f32 %0, %1;" : "=r"(u) : "f"(x));
    return __uint_as_float(u);
}

#define APITCH 36
#define OPITCH 132

// OUTH=0: fp32 output to `out`; OUTH=1: fp16 output to `hout`. Single path per
// instantiation so register pressure matches the known-good R7 kernel.
template <int K, int OUTH>
__global__ void __launch_bounds__(256)
gemm_ln_kernel(const float* __restrict__ A, const float* __restrict__ W,
               const float* __restrict__ b1, const float* __restrict__ b2,
               const float* __restrict__ lw, const float* __restrict__ lb,
               float* __restrict__ out, __half* __restrict__ hout, int M) {
    extern __shared__ float buf[];           // max(2*128*36, 128*132) = 16896 floats
    float* At = buf;                         // [128][36]
    float* Wt = buf + 128 * APITCH;
    __shared__ float sb[3][NC];

    int tid = threadIdx.x;
    int lane = tid & 31, wid = tid >> 5;
    int warp_m = wid >> 2, warp_n = wid & 3; // 2 x 4 warps
    int gid = lane >> 2, tig = lane & 3;
    int row0 = blockIdx.x * 128;

    if (tid < NC) {
        float c = b1[tid];
        if (b2) c += b2[tid];
        sb[0][tid] = c;
        sb[1][tid] = lw[tid];
        sb[2][tid] = lb[tid];
    }

    float acc[4][4][4];
#pragma unroll
    for (int i = 0; i < 4; i++)
#pragma unroll
        for (int j = 0; j < 4; j++)
#pragma unroll
            for (int c = 0; c < 4; c++) acc[i][j][c] = 0.f;

    for (int kc = 0; kc < K; kc += 32) {
#pragma unroll
        for (int it = 0; it < 4; it++) {
            int idx = tid + it * 256;        // 0..1023
            int r = idx >> 3, seg = idx & 7;
            float4 v = make_float4(0, 0, 0, 0);
            if (row0 + r < M)
                v = *(const float4*)(A + (size_t)(row0 + r) * K + kc + seg * 4);
            float* dp = At + r * APITCH + seg * 4;
            dp[0] = tf32r(v.x); dp[1] = tf32r(v.y); dp[2] = tf32r(v.z); dp[3] = tf32r(v.w);
            float4 w4 = *(const float4*)(W + (size_t)r * K + kc + seg * 4);
            float* dw = Wt + r * APITCH + seg * 4;
            dw[0] = tf32r(w4.x); dw[1] = tf32r(w4.y); dw[2] = tf32r(w4.z); dw[3] = tf32r(w4.w);
        }
        __syncthreads();
#pragma unroll
        for (int ks = 0; ks < 4; ks++) {
            int k = ks * 8;
            unsigned bfr[4][2];
#pragma unroll
            for (int j = 0; j < 4; j++) {
                int n0 = warp_n * 32 + j * 8;
                bfr[j][0] = __float_as_uint(Wt[(n0 + gid) * APITCH + k + tig]);
                bfr[j][1] = __float_as_uint(Wt[(n0 + gid) * APITCH + k + tig + 4]);
            }
#pragma unroll
            for (int i = 0; i < 4; i++) {
                int m0 = warp_m * 64 + i * 16;
                unsigned a0 = __float_as_uint(At[(m0 + gid) * APITCH + k + tig]);
                unsigned a1 = __float_as_uint(At[(m0 + gid + 8) * APITCH + k + tig]);
                unsigned a2 = __float_as_uint(At[(m0 + gid) * APITCH + k + tig + 4]);
                unsigned a3 = __float_as_uint(At[(m0 + gid + 8) * APITCH + k + tig + 4]);
#pragma unroll
                for (int j = 0; j < 4; j++) {
                    asm volatile(
                        "mma.sync.aligned.m16n8k8.row.col.f32.tf32.tf32.f32 "
                        "{%0,%1,%2,%3}, {%4,%5,%6,%7}, {%8,%9}, {%0,%1,%2,%3};\n"
                        : "+f"(acc[i][j][0]), "+f"(acc[i][j][1]),
                          "+f"(acc[i][j][2]), "+f"(acc[i][j][3])
                        : "r"(a0), "r"(a1), "r"(a2), "r"(a3),
                          "r"(bfr[j][0]), "r"(bfr[j][1]));
                }
            }
        }
        __syncthreads();
    }

    float* Ot = buf;                         // [128][132] aliases At/Wt
#pragma unroll
    for (int i = 0; i < 4; i++) {
        int m0 = warp_m * 64 + i * 16;
#pragma unroll
        for (int j = 0; j < 4; j++) {
            int n0 = warp_n * 32 + j * 8 + 2 * tig;
            Ot[(m0 + gid) * OPITCH + n0]         = acc[i][j][0];
            Ot[(m0 + gid) * OPITCH + n0 + 1]     = acc[i][j][1];
            Ot[(m0 + gid + 8) * OPITCH + n0]     = acc[i][j][2];
            Ot[(m0 + gid + 8) * OPITCH + n0 + 1] = acc[i][j][3];
        }
    }
    __syncthreads();

    int col = lane * 4;
    for (int rr = 0; rr < 16; rr++) {
        int r = wid * 16 + rr;
        int grow = row0 + r;
        if (grow >= M) break;
        float4 v = *(const float4*)&Ot[r * OPITCH + col];
        v.x += sb[0][col];     v.y += sb[0][col + 1];
        v.z += sb[0][col + 2]; v.w += sb[0][col + 3];
        float s = v.x + v.y + v.z + v.w;
#pragma unroll
        for (int o = 16; o > 0; o >>= 1) s += __shfl_xor_sync(0xffffffffu, s, o);
        float mu = s * (1.0f / NC);
        float dx = v.x - mu, dy = v.y - mu, dz = v.z - mu, dw = v.w - mu;
        float q = dx * dx + dy * dy + dz * dz + dw * dw;
#pragma unroll
        for (int o = 16; o > 0; o >>= 1) q += __shfl_xor_sync(0xffffffffu, q, o);
        float rs = rsqrtf(q * (1.0f / NC) + LN_EPS);
        float4 y;
        y.x = fmaxf(dx * rs * sb[1][col]     + sb[2][col],     0.f);
        y.y = fmaxf(dy * rs * sb[1][col + 1] + sb[2][col + 1], 0.f);
        y.z = fmaxf(dz * rs * sb[1][col + 2] + sb[2][col + 2], 0.f);
        y.w = fmaxf(dw * rs * sb[1][col + 3] + sb[2][col + 3], 0.f);
        if (OUTH) {
            uint2 u = make_uint2(pack2(y.x, y.y), pack2(y.z, y.w));
            *(uint2*)(hout + (size_t)grow * NC + col) = u;
        } else {
            *(float4*)(out + (size_t)grow * NC + col) = y;
        }
    }
}

// ---------------- launch ----------------
extern "C" void kernel_launch(void* const* d_in, const int* in_sizes, int n_in,
                              void* d_out, int out_size) {
    (void)in_sizes; (void)n_in; (void)out_size;
    const float* x_a      = (const float*)d_in[0];
    const float* x_b      = (const float*)d_in[1];
    const float* schema_x = (const float*)d_in[2];
    const int*   e_ab     = (const int*)d_in[3];
    const int*   e_ba     = (const int*)d_in[4];
    const int*   e_aa     = (const int*)d_in[5];
    const int*   sei      = (const int*)d_in[6];
    const float* pre_W    = (const float*)d_in[7];
    const float* pre_b    = (const float*)d_in[8];
    const float* gcn_W    = (const float*)d_in[9];
    const float* gcn_b    = (const float*)d_in[10];
    const float* coeff_W  = (const float*)d_in[11];
    const float* coeff_b  = (const float*)d_in[12];
    const float* bases    = (const float*)d_in[13];
    const float* sage_bias= (const float*)d_in[14];
    const float* ln_w     = (const float*)d_in[15];
    const float* ln_b     = (const float*)d_in[16];

    float* out = (float*)d_out;
    float* out_xa  = out;
    float* out_xb  = out + (size_t)N_NODES * NC;
    float* out_sf  = out + (size_t)2 * N_NODES * NC;
    float* out_ori = out_sf + NS * NH;

    float *p_mid_a, *p_mid_b, *p_Wab, *p_Wcat;
    int* p_pos;
    __half *p_ha, *p_hb;
    cudaGetSymbolAddress((void**)&p_mid_a, g_mid_a);
    cudaGetSymbolAddress((void**)&p_mid_b, g_mid_b);
    cudaGetSymbolAddress((void**)&p_ha,    g_ha);
    cudaGetSymbolAddress((void**)&p_hb,    g_hb);
    cudaGetSymbolAddress((void**)&p_Wab,   g_Wab);
    cudaGetSymbolAddress((void**)&p_Wcat,  g_Wcat);
    cudaGetSymbolAddress((void**)&p_pos,   g_pos);

    const int SMEM_GEMM = 16896 * sizeof(float);
    cudaFuncSetAttribute(gemm_ln_kernel<256, 0>,
                         cudaFuncAttributeMaxDynamicSharedMemorySize, SMEM_GEMM);
    cudaFuncSetAttribute(gemm_ln_kernel<128, 0>,
                         cudaFuncAttributeMaxDynamicSharedMemorySize, SMEM_GEMM);
    cudaFuncSetAttribute(gemm_ln_kernel<256, 1>,
                         cudaFuncAttributeMaxDynamicSharedMemorySize, SMEM_GEMM);
    cudaFuncSetAttribute(gemm_ln_kernel<128, 1>,
                         cudaFuncAttributeMaxDynamicSharedMemorySize, SMEM_GEMM);

    // ---- CSR build ----
    cudaMemsetAsync(p_pos, 0, sizeof(int) * 3 * N_NODES);
    hist3_kernel<<<3 * NE / 256, 256>>>(e_ab, e_ba, e_aa);
    scan1_kernel<<<3 * SCAN_NB, 1024>>>();
    scan2_kernel<<<1, 32>>>();
    scan3_kernel<<<3 * SCAN_NB, 1024>>>();
    fill3_kernel<<<3 * NE / 256, 256>>>(e_ab, e_ba, e_aa);

    // ---- schema + dynamic weights + fp16 input copies ----
    schema_kernel<<<1, 512>>>(schema_x, sei, pre_W, pre_b, gcn_W, gcn_b,
                              coeff_W, coeff_b, out_sf, out_ori);
    buildW_kernel<<<(2 * NC * NC + 255) / 256, 256>>>(bases);
    tohalf_kernel<<<(2 * N_NODES * NC / 8) / 256, 256>>>(x_a, x_b);

    const int AGG_GRID  = (2 * N_NODES * 32 + 255) / 256;
    const int GEMM_GRID = (N_NODES + 127) / 128;

    // ---- layer 0 (outputs only needed as fp16 for layer 1) ----
    agg_all_kernel<<<AGG_GRID, 256>>>(p_ha, p_hb, p_mid_a, p_mid_b);
    gemm_ln_kernel<256, 1><<<GEMM_GRID, 256, SMEM_GEMM>>>(
        p_mid_a, p_Wcat, sage_bias + 1 * NC, sage_bias + 2 * NC,
        ln_w + 0 * NC, ln_b + 0 * NC, nullptr, p_ha, N_NODES);
    gemm_ln_kernel<128, 1><<<GEMM_GRID, 256, SMEM_GEMM>>>(
        p_mid_b, p_Wab, sage_bias + 0 * NC, nullptr,
        ln_w + 1 * NC, ln_b + 1 * NC, nullptr, p_hb, N_NODES);

    // ---- layer 1 (fp32 outputs to d_out) ----
    agg_all_kernel<<<AGG_GRID, 256>>>(p_ha, p_hb, p_mid_a, p_mid_b);
    gemm_ln_kernel<256, 0><<<GEMM_GRID, 256, SMEM_GEMM>>>(
        p_mid_a, p_Wcat + NC * 256, sage_bias + 4 * NC, sage_bias + 5 * NC,
        ln_w + 2 * NC, ln_b + 2 * NC, out_xa, nullptr, N_NODES);
    gemm_ln_kernel<128, 0><<<GEMM_GRID, 256, SMEM_GEMM>>>(
        p_mid_b, p_Wab + NC * NC, sage_bias + 3 * NC, nullptr,
        ln_w + 3 * NC, ln_b + 3 * NC, out_xb, nullptr, N_NODES);
}

// round 9
// speedup vs baseline: 1.5229x; 1.0265x over previous
#include <cuda_runtime.h>
#include <cuda_fp16.h>
#include <cstddef>

#define N_NODES 50000
#define NC 128
#define NE 800000
#define NS 8
#define NH 64
#define NB_ 8
#define LN_EPS 1e-5f
#define SCAN_NB 13
#define SCAN_CHUNK 4096

// ---------------- scratch (device globals; no allocation) ----------------
__device__ int    g_off [3][N_NODES + 1];
__device__ int    g_pos [3][N_NODES];      // degree hist -> write cursors
__device__ int    g_bsum[3][SCAN_NB];
__device__ int    g_srcs[3][NE];
__device__ float  g_mid_a[(size_t)N_NODES * 256];
__device__ float  g_mid_b[(size_t)N_NODES * NC];
__device__ __half g_ha[(size_t)N_NODES * NC];
__device__ __half g_hb[(size_t)N_NODES * NC];
__device__ float  g_Wab [2][NC * NC];
__device__ float  g_Wcat[2][NC * 256];     // [j][0:128]=W_ba  [j][128:256]=W_aa
__device__ float  g_coeff[3][NB_];         // 0: ab, 1: ba, 2: aa

// ---------------- CSR build ----------------
__global__ void hist3_kernel(const int* __restrict__ e0, const int* __restrict__ e1,
                             const int* __restrict__ e2) {
    int i = blockIdx.x * blockDim.x + threadIdx.x;  // grid covers exactly 3*NE
    int t = i / NE, j = i % NE;
    const int* e = (t == 0) ? e0 : (t == 1) ? e1 : e2;
    atomicAdd(&g_pos[t][e[NE + j]], 1);
}

__global__ void scan1_kernel() {           // grid = 3*SCAN_NB, block = 1024
    int t = blockIdx.x / SCAN_NB, c = blockIdx.x % SCAN_NB;
    int base = c * SCAN_CHUNK;
    int tid = threadIdx.x;
    int v = 0;
#pragma unroll
    for (int i = 0; i < 4; i++) {
        int idx = base + tid * 4 + i;
        if (idx < N_NODES) v += g_pos[t][idx];
    }
#pragma unroll
    for (int o = 16; o > 0; o >>= 1) v += __shfl_xor_sync(0xffffffffu, v, o);
    __shared__ int ws[32];
    if ((tid & 31) == 0) ws[tid >> 5] = v;
    __syncthreads();
    if (tid < 32) {
        int s = ws[tid];
#pragma unroll
        for (int o = 16; o > 0; o >>= 1) s += __shfl_xor_sync(0xffffffffu, s, o);
        if (tid == 0) g_bsum[t][c] = s;
    }
}

__global__ void scan2_kernel() {
    if (threadIdx.x == 0) {
        for (int t = 0; t < 3; t++) {
            int run = 0;
            for (int c = 0; c < SCAN_NB; c++) {
                int v = g_bsum[t][c];
                g_bsum[t][c] = run;
                run += v;
            }
            g_off[t][N_NODES] = run;
        }
    }
}

__global__ void scan3_kernel() {           // grid = 3*SCAN_NB, block = 1024
    int t = blockIdx.x / SCAN_NB, c = blockIdx.x % SCAN_NB;
    int base = c * SCAN_CHUNK;
    int tid = threadIdx.x, lane = tid & 31, wid = tid >> 5;
    int v[4], s = 0;
#pragma unroll
    for (int i = 0; i < 4; i++) {
        int idx = base + tid * 4 + i;
        v[i] = (idx < N_NODES) ? g_pos[t][idx] : 0;
        s += v[i];
    }
    int si = s;
#pragma unroll
    for (int d = 1; d < 32; d <<= 1) {
        int n = __shfl_up_sync(0xffffffffu, si, d);
        if (lane >= d) si += n;
    }
    __shared__ int ws[32];
    if (lane == 31) ws[wid] = si;
    __syncthreads();
    if (wid == 0) {
        int w = ws[lane];
#pragma unroll
        for (int d = 1; d < 32; d <<= 1) {
            int n = __shfl_up_sync(0xffffffffu, w, d);
            if (lane >= d) w += n;
        }
        ws[lane] = w;
    }
    __syncthreads();
    int run = si - s + (wid ? ws[wid - 1] : 0) + g_bsum[t][c];
#pragma unroll
    for (int i = 0; i < 4; i++) {
        int idx = base + tid * 4 + i;
        if (idx < N_NODES) {
            g_off[t][idx] = run;
            g_pos[t][idx] = run;
            run += v[i];
        }
    }
}

__global__ void fill3_kernel(const int* __restrict__ e0, const int* __restrict__ e1,
                             const int* __restrict__ e2) {
    int i = blockIdx.x * blockDim.x + threadIdx.x;
    int t = i / NE, j = i % NE;
    const int* e = (t == 0) ? e0 : (t == 1) ? e1 : e2;
    int s = e[j], d = e[NE + j];
    int p = atomicAdd(&g_pos[t][d], 1);
    g_srcs[t][p] = s;
}

// ---------------- fp16 copies of the input tables ----------------
__device__ __forceinline__ unsigned pack2(float a, float b) {
    __half2 h = __floats2half2_rn(a, b);
    return *(unsigned*)&h;
}

__global__ void tohalf_kernel(const float* __restrict__ xa, const float* __restrict__ xb) {
    int i = blockIdx.x * blockDim.x + threadIdx.x;   // each handles 8 floats
    const size_t TOT = (size_t)N_NODES * NC;
    size_t base = (size_t)i * 8;
    const float* src;
    __half* dst;
    if (base < TOT) { src = xa + base; dst = g_ha + base; }
    else            { src = xb + (base - TOT); dst = g_hb + (base - TOT); }
    float4 v0 = *(const float4*)src;
    float4 v1 = *(const float4*)(src + 4);
    uint4 u = make_uint4(pack2(v0.x, v0.y), pack2(v0.z, v0.w),
                         pack2(v1.x, v1.y), pack2(v1.z, v1.w));
    *(uint4*)dst = u;
}

// ---------------- schema GCN + dynamic coefficients (1 block, 512 thr) ----------------
__global__ void schema_kernel(const float* __restrict__ schema_x, const int* __restrict__ sei,
                              const float* __restrict__ pre_W, const float* __restrict__ pre_b,
                              const float* __restrict__ gcn_W, const float* __restrict__ gcn_b,
                              const float* __restrict__ coeff_W, const float* __restrict__ coeff_b,
                              float* __restrict__ out_sf, float* __restrict__ out_ori) {
    __shared__ float h [NS][NH];
    __shared__ float xw[NS][NH];
    __shared__ float sf[NS][NH];
    __shared__ float dinv[NS];
    int tid = threadIdx.x;              // 512 = 8*64
    int s = tid / NH, j = tid % NH;

    float acc = pre_b[j];
    for (int i = 0; i < NH; i++) acc += schema_x[s * NH + i] * pre_W[j * NH + i];
    h[s][j] = acc;
    out_ori[s * NH + j] = acc;
    __syncthreads();

    float xacc = 0.f;
    for (int k = 0; k < NH; k++) xacc += h[s][k] * gcn_W[j * NH + k];
    xw[s][j] = xacc;
    if (tid < NS) {
        float d = 1.0f;
        for (int e = 0; e < 24; e++) if (sei[24 + e] == tid) d += 1.0f;
        dinv[tid] = rsqrtf(fmaxf(d, 1e-12f));
    }
    __syncthreads();

    float o = gcn_b[j] + dinv[s] * dinv[s] * xw[s][j];
    for (int e = 0; e < 24; e++) {
        int es = sei[e], ed = sei[24 + e];
        if (ed == s) o += dinv[es] * dinv[s] * xw[es][j];
    }
    o = fmaxf(o, 0.f);
    sf[s][j] = o;
    out_sf[s * NH + j] = o;
    __syncthreads();

    if (tid < 3 * NB_) {
        int t = tid / NB_, i = tid % NB_;
        int ssrc = (t == 1) ? 1 : 0;
        int sdst = (t == 0) ? 1 : 0;
        float c = coeff_b[i];
        for (int k = 0; k < NH; k++) c += sf[ssrc][k] * coeff_W[i * 128 + k];
        for (int k = 0; k < NH; k++) c += sf[sdst][k] * coeff_W[i * 128 + 64 + k];
        g_coeff[t][i] = c;
    }
}

__global__ void buildW_kernel(const float* __restrict__ bases) {
    int id = blockIdx.x * blockDim.x + threadIdx.x;
    if (id >= 2 * NC * NC) return;
    int l = id / (NC * NC);
    int jk = id % (NC * NC);
    int j = jk / NC, k = jk % NC;
    float wab = 0.f, wba = 0.f, waa = 0.f;
#pragma unroll
    for (int i = 0; i < NB_; i++) {
        float b = bases[(size_t)l * NB_ * NC * NC + (size_t)i * NC * NC + jk];
        wab += g_coeff[0][i] * b;
        wba += g_coeff[1][i] * b;
        waa += g_coeff[2][i] * b;
    }
    g_Wab[l][jk] = wab;
    g_Wcat[l][j * 256 + k] = wba;
    g_Wcat[l][j * 256 + 128 + k] = waa;
}

// ---------------- aggregation (fp16 sources, fp32 accum, MLP=8) ----------------
__device__ __forceinline__ void add_u2(uint2 u, float4& a) {
    __half2 h0 = *(__half2*)&u.x, h1 = *(__half2*)&u.y;
    float2 f0 = __half22float2(h0), f1 = __half22float2(h1);
    a.x += f0.x; a.y += f0.y; a.z += f1.x; a.w += f1.y;
}

__device__ __forceinline__ void add_rowh(const __half* __restrict__ p, float4& a) {
    add_u2(*(const uint2*)p, a);
}

__device__ __forceinline__ void acc_range(const __half* __restrict__ xsrc,
                                          const int* __restrict__ srcs,
                                          int beg, int end, int col, float4& out) {
    float4 a0 = make_float4(0, 0, 0, 0), a1 = a0, a2 = a0, a3 = a0;
    int e = beg;
    for (; e + 8 <= end; e += 8) {
        int s0 = srcs[e],     s1 = srcs[e + 1], s2 = srcs[e + 2], s3 = srcs[e + 3];
        int s4 = srcs[e + 4], s5 = srcs[e + 5], s6 = srcs[e + 6], s7 = srcs[e + 7];
        uint2 u0 = *(const uint2*)(xsrc + (size_t)s0 * NC + col);
        uint2 u1 = *(const uint2*)(xsrc + (size_t)s1 * NC + col);
        uint2 u2 = *(const uint2*)(xsrc + (size_t)s2 * NC + col);
        uint2 u3 = *(const uint2*)(xsrc + (size_t)s3 * NC + col);
        uint2 u4 = *(const uint2*)(xsrc + (size_t)s4 * NC + col);
        uint2 u5 = *(const uint2*)(xsrc + (size_t)s5 * NC + col);
        uint2 u6 = *(const uint2*)(xsrc + (size_t)s6 * NC + col);
        uint2 u7 = *(const uint2*)(xsrc + (size_t)s7 * NC + col);
        add_u2(u0, a0); add_u2(u1, a1); add_u2(u2, a2); add_u2(u3, a3);
        add_u2(u4, a0); add_u2(u5, a1); add_u2(u6, a2); add_u2(u7, a3);
    }
    if (e + 4 <= end) {
        int s0 = srcs[e], s1 = srcs[e + 1], s2 = srcs[e + 2], s3 = srcs[e + 3];
        uint2 u0 = *(const uint2*)(xsrc + (size_t)s0 * NC + col);
        uint2 u1 = *(const uint2*)(xsrc + (size_t)s1 * NC + col);
        uint2 u2 = *(const uint2*)(xsrc + (size_t)s2 * NC + col);
        uint2 u3 = *(const uint2*)(xsrc + (size_t)s3 * NC + col);
        add_u2(u0, a0); add_u2(u1, a1); add_u2(u2, a2); add_u2(u3, a3);
        e += 4;
    }
    for (; e < end; e++) add_rowh(xsrc + (size_t)srcs[e] * NC + col, a0);
    float inv = 1.0f / fmaxf((float)(end - beg), 1.0f);
    out.x = (a0.x + a1.x + a2.x + a3.x) * inv;
    out.y = (a0.y + a1.y + a2.y + a3.y) * inv;
    out.z = (a0.z + a1.z + a2.z + a3.z) * inv;
    out.w = (a0.w + a1.w + a2.w + a3.w) * inv;
}

// combined: warps [0,N) -> b-dst (ab edges); warps [N,2N) -> a-dst (ba+aa edges)
__global__ void agg_all_kernel(const __half* __restrict__ ha, const __half* __restrict__ hb,
                               float* __restrict__ mid_a, float* __restrict__ mid_b) {
    int g = blockIdx.x * blockDim.x + threadIdx.x;
    int w = g >> 5, lane = g & 31;
    int col = lane * 4;
    if (w < N_NODES) {
        int node = w;
        float4 m;
        acc_range(ha, g_srcs[0], g_off[0][node], g_off[0][node + 1], col, m);
        float4 xd = make_float4(0, 0, 0, 0);
        add_rowh(hb + (size_t)node * NC + col, xd);
        m.x += xd.x; m.y += xd.y; m.z += xd.z; m.w += xd.w;
        *(float4*)(mid_b + (size_t)node * NC + col) = m;
    } else if (w < 2 * N_NODES) {
        int node = w - N_NODES;
        float4 xd = make_float4(0, 0, 0, 0);
        add_rowh(ha + (size_t)node * NC + col, xd);
        float4 m0, m1;
        acc_range(hb, g_srcs[1], g_off[1][node], g_off[1][node + 1], col, m0);
        acc_range(ha, g_srcs[2], g_off[2][node], g_off[2][node + 1], col, m1);
        m0.x += xd.x; m0.y += xd.y; m0.z += xd.z; m0.w += xd.w;
        m1.x += xd.x; m1.y += xd.y; m1.z += xd.z; m1.w += xd.w;
        *(float4*)(mid_a + (size_t)node * 256 + col) = m0;
        *(float4*)(mid_a + (size_t)node * 256 + 128 + col) = m1;
    }
}

// ---------------- tf32 GEMM + bias + LayerNorm + ReLU fused ----------------
__device__ __forceinline__ float tf32r(float x) {
    unsigned u;
    asm("cvt.rna.tf32.f32 %0, %1;" : "=r"(u) : "f"(x));
    return __uint_as_float(u);
}

#define APITCH 36
#define OPITCH 132

// OUTH=0: fp32 output to `out`; OUTH=1: fp16 output to `hout`.
template <int K, int OUTH>
__global__ void __launch_bounds__(256)
gemm_ln_kernel(const float* __restrict__ A, const float* __restrict__ W,
               const float* __restrict__ b1, const float* __restrict__ b2,
               const float* __restrict__ lw, const float* __restrict__ lb,
               float* __restrict__ out, __half* __restrict__ hout, int M) {
    extern __shared__ float buf[];           // max(2*128*36, 128*132) = 16896 floats
    float* At = buf;                         // [128][36]
    float* Wt = buf + 128 * APITCH;
    __shared__ float sb[3][NC];

    int tid = threadIdx.x;
    int lane = tid & 31, wid = tid >> 5;
    int warp_m = wid >> 2, warp_n = wid & 3; // 2 x 4 warps
    int gid = lane >> 2, tig = lane & 3;
    int row0 = blockIdx.x * 128;

    if (tid < NC) {
        float c = b1[tid];
        if (b2) c += b2[tid];
        sb[0][tid] = c;
        sb[1][tid] = lw[tid];
        sb[2][tid] = lb[tid];
    }

    float acc[4][4][4];
#pragma unroll
    for (int i = 0; i < 4; i++)
#pragma unroll
        for (int j = 0; j < 4; j++)
#pragma unroll
            for (int c = 0; c < 4; c++) acc[i][j][c] = 0.f;

    for (int kc = 0; kc < K; kc += 32) {
#pragma unroll
        for (int it = 0; it < 4; it++) {
            int idx = tid + it * 256;        // 0..1023
            int r = idx >> 3, seg = idx & 7;
            float4 v = make_float4(0, 0, 0, 0);
            if (row0 + r < M)
                v = *(const float4*)(A + (size_t)(row0 + r) * K + kc + seg * 4);
            float* dp = At + r * APITCH + seg * 4;
            dp[0] = tf32r(v.x); dp[1] = tf32r(v.y); dp[2] = tf32r(v.z); dp[3] = tf32r(v.w);
            float4 w4 = *(const float4*)(W + (size_t)r * K + kc + seg * 4);
            float* dw = Wt + r * APITCH + seg * 4;
            dw[0] = tf32r(w4.x); dw[1] = tf32r(w4.y); dw[2] = tf32r(w4.z); dw[3] = tf32r(w4.w);
        }
        __syncthreads();
#pragma unroll
        for (int ks = 0; ks < 4; ks++) {
            int k = ks * 8;
            unsigned bfr[4][2];
#pragma unroll
            for (int j = 0; j < 4; j++) {
                int n0 = warp_n * 32 + j * 8;
                bfr[j][0] = __float_as_uint(Wt[(n0 + gid) * APITCH + k + tig]);
                bfr[j][1] = __float_as_uint(Wt[(n0 + gid) * APITCH + k + tig + 4]);
            }
#pragma unroll
            for (int i = 0; i < 4; i++) {
                int m0 = warp_m * 64 + i * 16;
                unsigned a0 = __float_as_uint(At[(m0 + gid) * APITCH + k + tig]);
                unsigned a1 = __float_as_uint(At[(m0 + gid + 8) * APITCH + k + tig]);
                unsigned a2 = __float_as_uint(At[(m0 + gid) * APITCH + k + tig + 4]);
                unsigned a3 = __float_as_uint(At[(m0 + gid + 8) * APITCH + k + tig + 4]);
#pragma unroll
                for (int j = 0; j < 4; j++) {
                    asm volatile(
                        "mma.sync.aligned.m16n8k8.row.col.f32.tf32.tf32.f32 "
                        "{%0,%1,%2,%3}, {%4,%5,%6,%7}, {%8,%9}, {%0,%1,%2,%3};\n"
                        : "+f"(acc[i][j][0]), "+f"(acc[i][j][1]),
                          "+f"(acc[i][j][2]), "+f"(acc[i][j][3])
                        : "r"(a0), "r"(a1), "r"(a2), "r"(a3),
                          "r"(bfr[j][0]), "r"(bfr[j][1]));
                }
            }
        }
        __syncthreads();
    }

    float* Ot = buf;                         // [128][132] aliases At/Wt
#pragma unroll
    for (int i = 0; i < 4; i++) {
        int m0 = warp_m * 64 + i * 16;
#pragma unroll
        for (int j = 0; j < 4; j++) {
            int n0 = warp_n * 32 + j * 8 + 2 * tig;
            Ot[(m0 + gid) * OPITCH + n0]         = acc[i][j][0];
            Ot[(m0 + gid) * OPITCH + n0 + 1]     = acc[i][j][1];
            Ot[(m0 + gid + 8) * OPITCH + n0]     = acc[i][j][2];
            Ot[(m0 + gid + 8) * OPITCH + n0 + 1] = acc[i][j][3];
        }
    }
    __syncthreads();

    int col = lane * 4;
    for (int rr = 0; rr < 16; rr++) {
        int r = wid * 16 + rr;
        int grow = row0 + r;
        if (grow >= M) break;
        float4 v = *(const float4*)&Ot[r * OPITCH + col];
        v.x += sb[0][col];     v.y += sb[0][col + 1];
        v.z += sb[0][col + 2]; v.w += sb[0][col + 3];
        float s = v.x + v.y + v.z + v.w;
#pragma unroll
        for (int o = 16; o > 0; o >>= 1) s += __shfl_xor_sync(0xffffffffu, s, o);
        float mu = s * (1.0f / NC);
        float dx = v.x - mu, dy = v.y - mu, dz = v.z - mu, dw = v.w - mu;
        float q = dx * dx + dy * dy + dz * dz + dw * dw;
#pragma unroll
        for (int o = 16; o > 0; o >>= 1) q += __shfl_xor_sync(0xffffffffu, q, o);
        float rs = rsqrtf(q * (1.0f / NC) + LN_EPS);
        float4 y;
        y.x = fmaxf(dx * rs * sb[1][col]     + sb[2][col],     0.f);
        y.y = fmaxf(dy * rs * sb[1][col + 1] + sb[2][col + 1], 0.f);
        y.z = fmaxf(dz * rs * sb[1][col + 2] + sb[2][col + 2], 0.f);
        y.w = fmaxf(dw * rs * sb[1][col + 3] + sb[2][col + 3], 0.f);
        if (OUTH) {
            uint2 u = make_uint2(pack2(y.x, y.y), pack2(y.z, y.w));
            *(uint2*)(hout + (size_t)grow * NC + col) = u;
        } else {
            *(float4*)(out + (size_t)grow * NC + col) = y;
        }
    }
}

// ---------------- launch ----------------
extern "C" void kernel_launch(void* const* d_in, const int* in_sizes, int n_in,
                              void* d_out, int out_size) {
    (void)in_sizes; (void)n_in; (void)out_size;
    const float* x_a      = (const float*)d_in[0];
    const float* x_b      = (const float*)d_in[1];
    const float* schema_x = (const float*)d_in[2];
    const int*   e_ab     = (const int*)d_in[3];
    const int*   e_ba     = (const int*)d_in[4];
    const int*   e_aa     = (const int*)d_in[5];
    const int*   sei      = (const int*)d_in[6];
    const float* pre_W    = (const float*)d_in[7];
    const float* pre_b    = (const float*)d_in[8];
    const float* gcn_W    = (const float*)d_in[9];
    const float* gcn_b    = (const float*)d_in[10];
    const float* coeff_W  = (const float*)d_in[11];
    const float* coeff_b  = (const float*)d_in[12];
    const float* bases    = (const float*)d_in[13];
    const float* sage_bias= (const float*)d_in[14];
    const float* ln_w     = (const float*)d_in[15];
    const float* ln_b     = (const float*)d_in[16];

    float* out = (float*)d_out;
    float* out_xa  = out;
    float* out_xb  = out + (size_t)N_NODES * NC;
    float* out_sf  = out + (size_t)2 * N_NODES * NC;
    float* out_ori = out_sf + NS * NH;

    float *p_mid_a, *p_mid_b, *p_Wab, *p_Wcat;
    int* p_pos;
    __half *p_ha, *p_hb;
    cudaGetSymbolAddress((void**)&p_mid_a, g_mid_a);
    cudaGetSymbolAddress((void**)&p_mid_b, g_mid_b);
    cudaGetSymbolAddress((void**)&p_ha,    g_ha);
    cudaGetSymbolAddress((void**)&p_hb,    g_hb);
    cudaGetSymbolAddress((void**)&p_Wab,   g_Wab);
    cudaGetSymbolAddress((void**)&p_Wcat,  g_Wcat);
    cudaGetSymbolAddress((void**)&p_pos,   g_pos);

    const int SMEM_GEMM = 16896 * sizeof(float);
    cudaFuncSetAttribute(gemm_ln_kernel<256, 0>,
                         cudaFuncAttributeMaxDynamicSharedMemorySize, SMEM_GEMM);
    cudaFuncSetAttribute(gemm_ln_kernel<128, 0>,
                         cudaFuncAttributeMaxDynamicSharedMemorySize, SMEM_GEMM);
    cudaFuncSetAttribute(gemm_ln_kernel<256, 1>,
                         cudaFuncAttributeMaxDynamicSharedMemorySize, SMEM_GEMM);
    cudaFuncSetAttribute(gemm_ln_kernel<128, 1>,
                         cudaFuncAttributeMaxDynamicSharedMemorySize, SMEM_GEMM);

    // ---- CSR build ----
    cudaMemsetAsync(p_pos, 0, sizeof(int) * 3 * N_NODES);
    hist3_kernel<<<3 * NE / 256, 256>>>(e_ab, e_ba, e_aa);
    scan1_kernel<<<3 * SCAN_NB, 1024>>>();
    scan2_kernel<<<1, 32>>>();
    scan3_kernel<<<3 * SCAN_NB, 1024>>>();
    fill3_kernel<<<3 * NE / 256, 256>>>(e_ab, e_ba, e_aa);

    // ---- schema + dynamic weights + fp16 input copies ----
    schema_kernel<<<1, 512>>>(schema_x, sei, pre_W, pre_b, gcn_W, gcn_b,
                              coeff_W, coeff_b, out_sf, out_ori);
    buildW_kernel<<<(2 * NC * NC + 255) / 256, 256>>>(bases);
    tohalf_kernel<<<(2 * N_NODES * NC / 8) / 256, 256>>>(x_a, x_b);

    const int AGG_GRID  = (2 * N_NODES * 32 + 255) / 256;
    const int GEMM_GRID = (N_NODES + 127) / 128;

    // ---- layer 0 (outputs only needed as fp16 for layer 1) ----
    agg_all_kernel<<<AGG_GRID, 256>>>(p_ha, p_hb, p_mid_a, p_mid_b);
    gemm_ln_kernel<256, 1><<<GEMM_GRID, 256, SMEM_GEMM>>>(
        p_mid_a, p_Wcat, sage_bias + 1 * NC, sage_bias + 2 * NC,
        ln_w + 0 * NC, ln_b + 0 * NC, nullptr, p_ha, N_NODES);
    gemm_ln_kernel<128, 1><<<GEMM_GRID, 256, SMEM_GEMM>>>(
        p_mid_b, p_Wab, sage_bias + 0 * NC, nullptr,
        ln_w + 1 * NC, ln_b + 1 * NC, nullptr, p_hb, N_NODES);

    // ---- layer 1 (fp32 outputs to d_out) ----
    agg_all_kernel<<<AGG_GRID, 256>>>(p_ha, p_hb, p_mid_a, p_mid_b);
    gemm_ln_kernel<256, 0><<<GEMM_GRID, 256, SMEM_GEMM>>>(
        p_mid_a, p_Wcat + NC * 256, sage_bias + 4 * NC, sage_bias + 5 * NC,
        ln_w + 2 * NC, ln_b + 2 * NC, out_xa, nullptr, N_NODES);
    gemm_ln_kernel<128, 0><<<GEMM_GRID, 256, SMEM_GEMM>>>(
        p_mid_b, p_Wab + NC * NC, sage_bias + 3 * NC, nullptr,
        ln_w + 3 * NC, ln_b + 3 * NC, out_xb, nullptr, N_NODES);
}

// round 10
// speedup vs baseline: 1.7326x; 1.1377x over previous
#include <cuda_runtime.h>
#include <cuda_fp16.h>
#include <cstddef>

#define N_NODES 50000
#define NC 128
#define NE 800000
#define NS 8
#define NH 64
#define NB_ 8
#define LN_EPS 1e-5f
#define SCAN_NB 13
#define SCAN_CHUNK 4096
#define HIST_BLOCKS (3 * NE / 256)
#define TOHALF_BLOCKS (2 * N_NODES * NC / 8 / 256)

// ---------------- scratch (device globals; no allocation) ----------------
__device__ int    g_off [3][N_NODES + 1];
__device__ int    g_pos [3][N_NODES];      // degree hist -> write cursors
__device__ int    g_bsum[3][SCAN_NB];
__device__ int    g_srcs[3][NE];
__device__ __half g_mid_a[(size_t)N_NODES * 256];
__device__ __half g_mid_b[(size_t)N_NODES * NC];
__device__ __half g_ha[(size_t)N_NODES * NC];
__device__ __half g_hb[(size_t)N_NODES * NC];
__device__ float  g_Wab [2][NC * NC];
__device__ float  g_Wcat[2][NC * 256];     // [j][0:128]=W_ba  [j][128:256]=W_aa
__device__ float  g_coeff[3][NB_];         // 0: ab, 1: ba, 2: aa

__device__ __forceinline__ unsigned pack2(float a, float b) {
    __half2 h = __floats2half2_rn(a, b);
    return *(unsigned*)&h;
}

// ---------------- hist + fp16 conversion fused ----------------
__global__ void hist_tohalf_kernel(const int* __restrict__ e0, const int* __restrict__ e1,
                                   const int* __restrict__ e2,
                                   const float* __restrict__ xa, const float* __restrict__ xb) {
    if (blockIdx.x < HIST_BLOCKS) {
        int i = blockIdx.x * blockDim.x + threadIdx.x;      // covers exactly 3*NE
        int t = i / NE, j = i % NE;
        const int* e = (t == 0) ? e0 : (t == 1) ? e1 : e2;
        atomicAdd(&g_pos[t][e[NE + j]], 1);
    } else {
        int i = (blockIdx.x - HIST_BLOCKS) * blockDim.x + threadIdx.x;  // 8 floats each
        const size_t TOT = (size_t)N_NODES * NC;
        size_t base = (size_t)i * 8;
        const float* src;
        __half* dst;
        if (base < TOT) { src = xa + base; dst = g_ha + base; }
        else            { src = xb + (base - TOT); dst = g_hb + (base - TOT); }
        float4 v0 = *(const float4*)src;
        float4 v1 = *(const float4*)(src + 4);
        uint4 u = make_uint4(pack2(v0.x, v0.y), pack2(v0.z, v0.w),
                             pack2(v1.x, v1.y), pack2(v1.z, v1.w));
        *(uint4*)dst = u;
    }
}

// ---------------- CSR scan ----------------
__global__ void scan1_kernel() {           // grid = 3*SCAN_NB, block = 1024
    int t = blockIdx.x / SCAN_NB, c = blockIdx.x % SCAN_NB;
    int base = c * SCAN_CHUNK;
    int tid = threadIdx.x;
    int v = 0;
#pragma unroll
    for (int i = 0; i < 4; i++) {
        int idx = base + tid * 4 + i;
        if (idx < N_NODES) v += g_pos[t][idx];
    }
#pragma unroll
    for (int o = 16; o > 0; o >>= 1) v += __shfl_xor_sync(0xffffffffu, v, o);
    __shared__ int ws[32];
    if ((tid & 31) == 0) ws[tid >> 5] = v;
    __syncthreads();
    if (tid < 32) {
        int s = ws[tid];
#pragma unroll
        for (int o = 16; o > 0; o >>= 1) s += __shfl_xor_sync(0xffffffffu, s, o);
        if (tid == 0) g_bsum[t][c] = s;
    }
}

__global__ void scan3_kernel() {           // grid = 3*SCAN_NB, block = 1024
    int t = blockIdx.x / SCAN_NB, c = blockIdx.x % SCAN_NB;
    int base = c * SCAN_CHUNK;
    int tid = threadIdx.x, lane = tid & 31, wid = tid >> 5;
    __shared__ int chunk_base;
    if (tid == 0) {
        int run = 0, mine = 0;
        for (int k = 0; k < SCAN_NB; k++) {
            if (k == c) mine = run;
            run += g_bsum[t][k];
        }
        chunk_base = mine;
        if (c == SCAN_NB - 1) g_off[t][N_NODES] = run;
    }
    int v[4], s = 0;
#pragma unroll
    for (int i = 0; i < 4; i++) {
        int idx = base + tid * 4 + i;
        v[i] = (idx < N_NODES) ? g_pos[t][idx] : 0;
        s += v[i];
    }
    int si = s;
#pragma unroll
    for (int d = 1; d < 32; d <<= 1) {
        int n = __shfl_up_sync(0xffffffffu, si, d);
        if (lane >= d) si += n;
    }
    __shared__ int ws[32];
    if (lane == 31) ws[wid] = si;
    __syncthreads();
    if (wid == 0) {
        int w = ws[lane];
#pragma unroll
        for (int d = 1; d < 32; d <<= 1) {
            int n = __shfl_up_sync(0xffffffffu, w, d);
            if (lane >= d) w += n;
        }
        ws[lane] = w;
    }
    __syncthreads();
    int run = si - s + (wid ? ws[wid - 1] : 0) + chunk_base;
#pragma unroll
    for (int i = 0; i < 4; i++) {
        int idx = base + tid * 4 + i;
        if (idx < N_NODES) {
            g_off[t][idx] = run;
            g_pos[t][idx] = run;
            run += v[i];
        }
    }
}

__global__ void fill3_kernel(const int* __restrict__ e0, const int* __restrict__ e1,
                             const int* __restrict__ e2) {
    int i = blockIdx.x * blockDim.x + threadIdx.x;
    int t = i / NE, j = i % NE;
    const int* e = (t == 0) ? e0 : (t == 1) ? e1 : e2;
    int s = e[j], d = e[NE + j];
    int p = atomicAdd(&g_pos[t][d], 1);
    g_srcs[t][p] = s;
}

// ---------------- schema GCN + dynamic coefficients (1 block, 512 thr) ----------------
__global__ void schema_kernel(const float* __restrict__ schema_x, const int* __restrict__ sei,
                              const float* __restrict__ pre_W, const float* __restrict__ pre_b,
                              const float* __restrict__ gcn_W, const float* __restrict__ gcn_b,
                              const float* __restrict__ coeff_W, const float* __restrict__ coeff_b,
                              float* __restrict__ out_sf, float* __restrict__ out_ori) {
    __shared__ float h [NS][NH];
    __shared__ float xw[NS][NH];
    __shared__ float sf[NS][NH];
    __shared__ float dinv[NS];
    int tid = threadIdx.x;              // 512 = 8*64
    int s = tid / NH, j = tid % NH;

    float acc = pre_b[j];
    for (int i = 0; i < NH; i++) acc += schema_x[s * NH + i] * pre_W[j * NH + i];
    h[s][j] = acc;
    out_ori[s * NH + j] = acc;
    __syncthreads();

    float xacc = 0.f;
    for (int k = 0; k < NH; k++) xacc += h[s][k] * gcn_W[j * NH + k];
    xw[s][j] = xacc;
    if (tid < NS) {
        float d = 1.0f;
        for (int e = 0; e < 24; e++) if (sei[24 + e] == tid) d += 1.0f;
        dinv[tid] = rsqrtf(fmaxf(d, 1e-12f));
    }
    __syncthreads();

    float o = gcn_b[j] + dinv[s] * dinv[s] * xw[s][j];
    for (int e = 0; e < 24; e++) {
        int es = sei[e], ed = sei[24 + e];
        if (ed == s) o += dinv[es] * dinv[s] * xw[es][j];
    }
    o = fmaxf(o, 0.f);
    sf[s][j] = o;
    out_sf[s * NH + j] = o;
    __syncthreads();

    if (tid < 3 * NB_) {
        int t = tid / NB_, i = tid % NB_;
        int ssrc = (t == 1) ? 1 : 0;
        int sdst = (t == 0) ? 1 : 0;
        float c = coeff_b[i];
        for (int k = 0; k < NH; k++) c += sf[ssrc][k] * coeff_W[i * 128 + k];
        for (int k = 0; k < NH; k++) c += sf[sdst][k] * coeff_W[i * 128 + 64 + k];
        g_coeff[t][i] = c;
    }
}

__global__ void buildW_kernel(const float* __restrict__ bases) {
    int id = blockIdx.x * blockDim.x + threadIdx.x;
    if (id >= 2 * NC * NC) return;
    int l = id / (NC * NC);
    int jk = id % (NC * NC);
    int j = jk / NC, k = jk % NC;
    float wab = 0.f, wba = 0.f, waa = 0.f;
#pragma unroll
    for (int i = 0; i < NB_; i++) {
        float b = bases[(size_t)l * NB_ * NC * NC + (size_t)i * NC * NC + jk];
        wab += g_coeff[0][i] * b;
        wba += g_coeff[1][i] * b;
        waa += g_coeff[2][i] * b;
    }
    g_Wab[l][jk] = wab;
    g_Wcat[l][j * 256 + k] = wba;
    g_Wcat[l][j * 256 + 128 + k] = waa;
}

// ---------------- aggregation (fp16 sources, fp32 accum, MLP=8, fp16 out) ----------------
__device__ __forceinline__ void add_u2(uint2 u, float4& a) {
    __half2 h0 = *(__half2*)&u.x, h1 = *(__half2*)&u.y;
    float2 f0 = __half22float2(h0), f1 = __half22float2(h1);
    a.x += f0.x; a.y += f0.y; a.z += f1.x; a.w += f1.y;
}

__device__ __forceinline__ void add_rowh(const __half* __restrict__ p, float4& a) {
    add_u2(*(const uint2*)p, a);
}

__device__ __forceinline__ void acc_range(const __half* __restrict__ xsrc,
                                          const int* __restrict__ srcs,
                                          int beg, int end, int col, float4& out) {
    float4 a0 = make_float4(0, 0, 0, 0), a1 = a0, a2 = a0, a3 = a0;
    int e = beg;
    for (; e + 8 <= end; e += 8) {
        int s0 = srcs[e],     s1 = srcs[e + 1], s2 = srcs[e + 2], s3 = srcs[e + 3];
        int s4 = srcs[e + 4], s5 = srcs[e + 5], s6 = srcs[e + 6], s7 = srcs[e + 7];
        uint2 u0 = *(const uint2*)(xsrc + (size_t)s0 * NC + col);
        uint2 u1 = *(const uint2*)(xsrc + (size_t)s1 * NC + col);
        uint2 u2 = *(const uint2*)(xsrc + (size_t)s2 * NC + col);
        uint2 u3 = *(const uint2*)(xsrc + (size_t)s3 * NC + col);
        uint2 u4 = *(const uint2*)(xsrc + (size_t)s4 * NC + col);
        uint2 u5 = *(const uint2*)(xsrc + (size_t)s5 * NC + col);
        uint2 u6 = *(const uint2*)(xsrc + (size_t)s6 * NC + col);
        uint2 u7 = *(const uint2*)(xsrc + (size_t)s7 * NC + col);
        add_u2(u0, a0); add_u2(u1, a1); add_u2(u2, a2); add_u2(u3, a3);
        add_u2(u4, a0); add_u2(u5, a1); add_u2(u6, a2); add_u2(u7, a3);
    }
    if (e + 4 <= end) {
        int s0 = srcs[e], s1 = srcs[e + 1], s2 = srcs[e + 2], s3 = srcs[e + 3];
        uint2 u0 = *(const uint2*)(xsrc + (size_t)s0 * NC + col);
        uint2 u1 = *(const uint2*)(xsrc + (size_t)s1 * NC + col);
        uint2 u2 = *(const uint2*)(xsrc + (size_t)s2 * NC + col);
        uint2 u3 = *(const uint2*)(xsrc + (size_t)s3 * NC + col);
        add_u2(u0, a0); add_u2(u1, a1); add_u2(u2, a2); add_u2(u3, a3);
        e += 4;
    }
    for (; e < end; e++) add_rowh(xsrc + (size_t)srcs[e] * NC + col, a0);
    float inv = 1.0f / fmaxf((float)(end - beg), 1.0f);
    out.x = (a0.x + a1.x + a2.x + a3.x) * inv;
    out.y = (a0.y + a1.y + a2.y + a3.y) * inv;
    out.z = (a0.z + a1.z + a2.z + a3.z) * inv;
    out.w = (a0.w + a1.w + a2.w + a3.w) * inv;
}

// combined: warps [0,N) -> b-dst (ab edges); warps [N,2N) -> a-dst (ba+aa edges)
__global__ void agg_all_kernel(const __half* __restrict__ ha, const __half* __restrict__ hb,
                               __half* __restrict__ mid_a, __half* __restrict__ mid_b) {
    int g = blockIdx.x * blockDim.x + threadIdx.x;
    int w = g >> 5, lane = g & 31;
    int col = lane * 4;
    if (w < N_NODES) {
        int node = w;
        float4 m;
        acc_range(ha, g_srcs[0], g_off[0][node], g_off[0][node + 1], col, m);
        float4 xd = make_float4(0, 0, 0, 0);
        add_rowh(hb + (size_t)node * NC + col, xd);
        m.x += xd.x; m.y += xd.y; m.z += xd.z; m.w += xd.w;
        uint2 u = make_uint2(pack2(m.x, m.y), pack2(m.z, m.w));
        *(uint2*)(mid_b + (size_t)node * NC + col) = u;
    } else if (w < 2 * N_NODES) {
        int node = w - N_NODES;
        float4 xd = make_float4(0, 0, 0, 0);
        add_rowh(ha + (size_t)node * NC + col, xd);
        float4 m0, m1;
        acc_range(hb, g_srcs[1], g_off[1][node], g_off[1][node + 1], col, m0);
        acc_range(ha, g_srcs[2], g_off[2][node], g_off[2][node + 1], col, m1);
        m0.x += xd.x; m0.y += xd.y; m0.z += xd.z; m0.w += xd.w;
        m1.x += xd.x; m1.y += xd.y; m1.z += xd.z; m1.w += xd.w;
        uint2 u0 = make_uint2(pack2(m0.x, m0.y), pack2(m0.z, m0.w));
        uint2 u1 = make_uint2(pack2(m1.x, m1.y), pack2(m1.z, m1.w));
        *(uint2*)(mid_a + (size_t)node * 256 + col) = u0;
        *(uint2*)(mid_a + (size_t)node * 256 + 128 + col) = u1;
    }
}

// ---------------- tf32 GEMM + bias + LayerNorm + ReLU fused ----------------
__device__ __forceinline__ float tf32r(float x) {
    unsigned u;
    asm("cvt.rna.tf32.f32 %0, %1;" : "=r"(u) : "f"(x));
    return __uint_as_float(u);
}

#define APITCH 36
#define OPITCH 132

// A is fp16; W fp32. OUTH=0: fp32 output to `out`; OUTH=1: fp16 output to `hout`.
template <int K, int OUTH>
__global__ void __launch_bounds__(256)
gemm_ln_kernel(const __half* __restrict__ A, const float* __restrict__ W,
               const float* __restrict__ b1, const float* __restrict__ b2,
               const float* __restrict__ lw, const float* __restrict__ lb,
               float* __restrict__ out, __half* __restrict__ hout, int M) {
    extern __shared__ float buf[];           // max(2*128*36, 128*132) = 16896 floats
    float* At = buf;                         // [128][36]
    float* Wt = buf + 128 * APITCH;
    __shared__ float sb[3][NC];

    int tid = threadIdx.x;
    int lane = tid & 31, wid = tid >> 5;
    int warp_m = wid >> 2, warp_n = wid & 3; // 2 x 4 warps
    int gid = lane >> 2, tig = lane & 3;
    int row0 = blockIdx.x * 128;

    if (tid < NC) {
        float c = b1[tid];
        if (b2) c += b2[tid];
        sb[0][tid] = c;
        sb[1][tid] = lw[tid];
        sb[2][tid] = lb[tid];
    }

    float acc[4][4][4];
#pragma unroll
    for (int i = 0; i < 4; i++)
#pragma unroll
        for (int j = 0; j < 4; j++)
#pragma unroll
            for (int c = 0; c < 4; c++) acc[i][j][c] = 0.f;

    for (int kc = 0; kc < K; kc += 32) {
#pragma unroll
        for (int it = 0; it < 4; it++) {
            int idx = tid + it * 256;        // 0..1023
            int r = idx >> 3, seg = idx & 7;
            float4 v = make_float4(0, 0, 0, 0);
            if (row0 + r < M) {
                uint2 ua = *(const uint2*)(A + (size_t)(row0 + r) * K + kc + seg * 4);
                __half2 h0 = *(__half2*)&ua.x, h1 = *(__half2*)&ua.y;
                float2 f0 = __half22float2(h0), f1 = __half22float2(h1);
                v = make_float4(f0.x, f0.y, f1.x, f1.y);
            }
            float* dp = At + r * APITCH + seg * 4;
            dp[0] = tf32r(v.x); dp[1] = tf32r(v.y); dp[2] = tf32r(v.z); dp[3] = tf32r(v.w);
            float4 w4 = *(const float4*)(W + (size_t)r * K + kc + seg * 4);
            float* dw = Wt + r * APITCH + seg * 4;
            dw[0] = tf32r(w4.x); dw[1] = tf32r(w4.y); dw[2] = tf32r(w4.z); dw[3] = tf32r(w4.w);
        }
        __syncthreads();
#pragma unroll
        for (int ks = 0; ks < 4; ks++) {
            int k = ks * 8;
            unsigned bfr[4][2];
#pragma unroll
            for (int j = 0; j < 4; j++) {
                int n0 = warp_n * 32 + j * 8;
                bfr[j][0] = __float_as_uint(Wt[(n0 + gid) * APITCH + k + tig]);
                bfr[j][1] = __float_as_uint(Wt[(n0 + gid) * APITCH + k + tig + 4]);
            }
#pragma unroll
            for (int i = 0; i < 4; i++) {
                int m0 = warp_m * 64 + i * 16;
                unsigned a0 = __float_as_uint(At[(m0 + gid) * APITCH + k + tig]);
                unsigned a1 = __float_as_uint(At[(m0 + gid + 8) * APITCH + k + tig]);
                unsigned a2 = __float_as_uint(At[(m0 + gid) * APITCH + k + tig + 4]);
                unsigned a3 = __float_as_uint(At[(m0 + gid + 8) * APITCH + k + tig + 4]);
#pragma unroll
                for (int j = 0; j < 4; j++) {
                    asm volatile(
                        "mma.sync.aligned.m16n8k8.row.col.f32.tf32.tf32.f32 "
                        "{%0,%1,%2,%3}, {%4,%5,%6,%7}, {%8,%9}, {%0,%1,%2,%3};\n"
                        : "+f"(acc[i][j][0]), "+f"(acc[i][j][1]),
                          "+f"(acc[i][j][2]), "+f"(acc[i][j][3])
                        : "r"(a0), "r"(a1), "r"(a2), "r"(a3),
                          "r"(bfr[j][0]), "r"(bfr[j][1]));
                }
            }
        }
        __syncthreads();
    }

    float* Ot = buf;                         // [128][132] aliases At/Wt
#pragma unroll
    for (int i = 0; i < 4; i++) {
        int m0 = warp_m * 64 + i * 16;
#pragma unroll
        for (int j = 0; j < 4; j++) {
            int n0 = warp_n * 32 + j * 8 + 2 * tig;
            Ot[(m0 + gid) * OPITCH + n0]         = acc[i][j][0];
            Ot[(m0 + gid) * OPITCH + n0 + 1]     = acc[i][j][1];
            Ot[(m0 + gid + 8) * OPITCH + n0]     = acc[i][j][2];
            Ot[(m0 + gid + 8) * OPITCH + n0 + 1] = acc[i][j][3];
        }
    }
    __syncthreads();

    int col = lane * 4;
    for (int rr = 0; rr < 16; rr++) {
        int r = wid * 16 + rr;
        int grow = row0 + r;
        if (grow >= M) break;
        float4 v = *(const float4*)&Ot[r * OPITCH + col];
        v.x += sb[0][col];     v.y += sb[0][col + 1];
        v.z += sb[0][col + 2]; v.w += sb[0][col + 3];
        float s = v.x + v.y + v.z + v.w;
#pragma unroll
        for (int o = 16; o > 0; o >>= 1) s += __shfl_xor_sync(0xffffffffu, s, o);
        float mu = s * (1.0f / NC);
        float dx = v.x - mu, dy = v.y - mu, dz = v.z - mu, dw = v.w - mu;
        float q = dx * dx + dy * dy + dz * dz + dw * dw;
#pragma unroll
        for (int o = 16; o > 0; o >>= 1) q += __shfl_xor_sync(0xffffffffu, q, o);
        float rs = rsqrtf(q * (1.0f / NC) + LN_EPS);
        float4 y;
        y.x = fmaxf(dx * rs * sb[1][col]     + sb[2][col],     0.f);
        y.y = fmaxf(dy * rs * sb[1][col + 1] + sb[2][col + 1], 0.f);
        y.z = fmaxf(dz * rs * sb[1][col + 2] + sb[2][col + 2], 0.f);
        y.w = fmaxf(dw * rs * sb[1][col + 3] + sb[2][col + 3], 0.f);
        if (OUTH) {
            uint2 u = make_uint2(pack2(y.x, y.y), pack2(y.z, y.w));
            *(uint2*)(hout + (size_t)grow * NC + col) = u;
        } else {
            *(float4*)(out + (size_t)grow * NC + col) = y;
        }
    }
}

// ---------------- launch ----------------
extern "C" void kernel_launch(void* const* d_in, const int* in_sizes, int n_in,
                              void* d_out, int out_size) {
    (void)in_sizes; (void)n_in; (void)out_size;
    const float* x_a      = (const float*)d_in[0];
    const float* x_b      = (const float*)d_in[1];
    const float* schema_x = (const float*)d_in[2];
    const int*   e_ab     = (const int*)d_in[3];
    const int*   e_ba     = (const int*)d_in[4];
    const int*   e_aa     = (const int*)d_in[5];
    const int*   sei      = (const int*)d_in[6];
    const float* pre_W    = (const float*)d_in[7];
    const float* pre_b    = (const float*)d_in[8];
    const float* gcn_W    = (const float*)d_in[9];
    const float* gcn_b    = (const float*)d_in[10];
    const float* coeff_W  = (const float*)d_in[11];
    const float* coeff_b  = (const float*)d_in[12];
    const float* bases    = (const float*)d_in[13];
    const float* sage_bias= (const float*)d_in[14];
    const float* ln_w     = (const float*)d_in[15];
    const float* ln_b     = (const float*)d_in[16];

    float* out = (float*)d_out;
    float* out_xa  = out;
    float* out_xb  = out + (size_t)N_NODES * NC;
    float* out_sf  = out + (size_t)2 * N_NODES * NC;
    float* out_ori = out_sf + NS * NH;

    float *p_Wab, *p_Wcat;
    int* p_pos;
    __half *p_ha, *p_hb, *p_mid_a, *p_mid_b;
    cudaGetSymbolAddress((void**)&p_mid_a, g_mid_a);
    cudaGetSymbolAddress((void**)&p_mid_b, g_mid_b);
    cudaGetSymbolAddress((void**)&p_ha,    g_ha);
    cudaGetSymbolAddress((void**)&p_hb,    g_hb);
    cudaGetSymbolAddress((void**)&p_Wab,   g_Wab);
    cudaGetSymbolAddress((void**)&p_Wcat,  g_Wcat);
    cudaGetSymbolAddress((void**)&p_pos,   g_pos);

    const int SMEM_GEMM = 16896 * sizeof(float);
    cudaFuncSetAttribute(gemm_ln_kernel<256, 0>,
                         cudaFuncAttributeMaxDynamicSharedMemorySize, SMEM_GEMM);
    cudaFuncSetAttribute(gemm_ln_kernel<128, 0>,
                         cudaFuncAttributeMaxDynamicSharedMemorySize, SMEM_GEMM);
    cudaFuncSetAttribute(gemm_ln_kernel<256, 1>,
                         cudaFuncAttributeMaxDynamicSharedMemorySize, SMEM_GEMM);
    cudaFuncSetAttribute(gemm_ln_kernel<128, 1>,
                         cudaFuncAttributeMaxDynamicSharedMemorySize, SMEM_GEMM);

    // ---- CSR build + fp16 conversion ----
    cudaMemsetAsync(p_pos, 0, sizeof(int) * 3 * N_NODES);
    hist_tohalf_kernel<<<HIST_BLOCKS + TOHALF_BLOCKS, 256>>>(e_ab, e_ba, e_aa, x_a, x_b);
    scan1_kernel<<<3 * SCAN_NB, 1024>>>();
    scan3_kernel<<<3 * SCAN_NB, 1024>>>();
    fill3_kernel<<<3 * NE / 256, 256>>>(e_ab, e_ba, e_aa);

    // ---- schema + dynamic weights ----
    schema_kernel<<<1, 512>>>(schema_x, sei, pre_W, pre_b, gcn_W, gcn_b,
                              coeff_W, coeff_b, out_sf, out_ori);
    buildW_kernel<<<(2 * NC * NC + 255) / 256, 256>>>(bases);

    const int AGG_GRID  = (2 * N_NODES * 32 + 255) / 256;
    const int GEMM_GRID = (N_NODES + 127) / 128;

    // ---- layer 0 (outputs only needed as fp16 for layer 1) ----
    agg_all_kernel<<<AGG_GRID, 256>>>(p_ha, p_hb, p_mid_a, p_mid_b);
    gemm_ln_kernel<256, 1><<<GEMM_GRID, 256, SMEM_GEMM>>>(
        p_mid_a, p_Wcat, sage_bias + 1 * NC, sage_bias + 2 * NC,
        ln_w + 0 * NC, ln_b + 0 * NC, nullptr, p_ha, N_NODES);
    gemm_ln_kernel<128, 1><<<GEMM_GRID, 256, SMEM_GEMM>>>(
        p_mid_b, p_Wab, sage_bias + 0 * NC, nullptr,
        ln_w + 1 * NC, ln_b + 1 * NC, nullptr, p_hb, N_NODES);

    // ---- layer 1 (fp32 outputs to d_out) ----
    agg_all_kernel<<<AGG_GRID, 256>>>(p_ha, p_hb, p_mid_a, p_mid_b);
    gemm_ln_kernel<256, 0><<<GEMM_GRID, 256, SMEM_GEMM>>>(
        p_mid_a, p_Wcat + NC * 256, sage_bias + 4 * NC, sage_bias + 5 * NC,
        ln_w + 2 * NC, ln_b + 2 * NC, out_xa, nullptr, N_NODES);
    gemm_ln_kernel<128, 0><<<GEMM_GRID, 256, SMEM_GEMM>>>(
        p_mid_b, p_Wab + NC * NC, sage_bias + 3 * NC, nullptr,
        ln_w + 3 * NC, ln_b + 3 * NC, out_xb, nullptr, N_NODES);
}

// round 14
// speedup vs baseline: 1.8371x; 1.0603x over previous
#include <cuda_runtime.h>
#include <cuda_fp16.h>
#include <cstddef>

#define N_NODES 50000
#define NC 128
#define NE 800000
#define NS 8
#define NH 64
#define NB_ 8
#define LN_EPS 1e-5f
#define SCAN_NB 13
#define SCAN_CHUNK 4096
#define HIST_BLOCKS (3 * NE / 256)
#define TOHALF_BLOCKS (2 * N_NODES * NC / 8 / 256)

// ---------------- scratch (device globals; no allocation) ----------------
// g_zero_base = [ pos(3*N) | flags(64) ]  — zeroed by one memset per launch
__device__ int    g_zero_base[3 * N_NODES + 64];
__device__ int    g_off [3][N_NODES + 1];
__device__ int    g_bsum[3][SCAN_NB];
__device__ int    g_srcs[3][NE];
__device__ __half g_mid_a[(size_t)N_NODES * 256];
__device__ __half g_mid_b[(size_t)N_NODES * NC];
__device__ __half g_ha[(size_t)N_NODES * NC];
__device__ __half g_hb[(size_t)N_NODES * NC];
__device__ __half g_Wab [2][NC * NC];
__device__ __half g_Wcat[2][NC * 256];     // [j][0:128]=W_ba  [j][128:256]=W_aa
__device__ float  g_coeff[3][NB_];         // 0: ab, 1: ba, 2: aa

__device__ __forceinline__ int* pos_ptr(int t) { return g_zero_base + t * N_NODES; }
#define FLAGS (g_zero_base + 3 * N_NODES)

__device__ __forceinline__ unsigned pack2(float a, float b) {
    __half2 h = __floats2half2_rn(a, b);
    return *(unsigned*)&h;
}

// ---------------- hist + fp16 conversion fused ----------------
__global__ void hist_tohalf_kernel(const int* __restrict__ e0, const int* __restrict__ e1,
                                   const int* __restrict__ e2,
                                   const float* __restrict__ xa, const float* __restrict__ xb) {
    if (blockIdx.x < HIST_BLOCKS) {
        int i = blockIdx.x * blockDim.x + threadIdx.x;      // covers exactly 3*NE
        int t = i / NE, j = i % NE;
        const int* e = (t == 0) ? e0 : (t == 1) ? e1 : e2;
        atomicAdd(&pos_ptr(t)[e[NE + j]], 1);
    } else {
        int i = (blockIdx.x - HIST_BLOCKS) * blockDim.x + threadIdx.x;  // 8 floats each
        const size_t TOT = (size_t)N_NODES * NC;
        size_t base = (size_t)i * 8;
        const float* src;
        __half* dst;
        if (base < TOT) { src = xa + base; dst = g_ha + base; }
        else            { src = xb + (base - TOT); dst = g_hb + (base - TOT); }
        float4 v0 = *(const float4*)src;
        float4 v1 = *(const float4*)(src + 4);
        uint4 u = make_uint4(pack2(v0.x, v0.y), pack2(v0.z, v0.w),
                             pack2(v1.x, v1.y), pack2(v1.z, v1.w));
        *(uint4*)dst = u;
    }
}

// ---------------- fused CSR scan: one kernel, 39 resident blocks ----------------
__global__ void scan_fused_kernel() {       // grid = 3*SCAN_NB, block = 1024
    int t = blockIdx.x / SCAN_NB, c = blockIdx.x % SCAN_NB;
    int base = c * SCAN_CHUNK;
    int tid = threadIdx.x, lane = tid & 31, wid = tid >> 5;
    int* pos = pos_ptr(t);

    int v[4], s = 0;
#pragma unroll
    for (int i = 0; i < 4; i++) {
        int idx = base + tid * 4 + i;
        v[i] = (idx < N_NODES) ? pos[idx] : 0;
        s += v[i];
    }

    // block total
    int r = s;
#pragma unroll
    for (int o = 16; o > 0; o >>= 1) r += __shfl_xor_sync(0xffffffffu, r, o);
    __shared__ int ws[32];
    if (lane == 0) ws[wid] = r;
    __syncthreads();

    __shared__ int chunk_base;
    if (tid == 0) {
        int tot = 0;
#pragma unroll
        for (int w = 0; w < 32; w++) tot += ws[w];
        g_bsum[t][c] = tot;
        __threadfence();
        atomicExch(&FLAGS[t * 16 + c], 1);
        // wait for all chunks of this edge type
        for (int k = 0; k < SCAN_NB; k++) {
            volatile int* f = &FLAGS[t * 16 + k];
            while (*f == 0) { }
        }
        __threadfence();
        int run = 0, mine = 0;
        for (int k = 0; k < SCAN_NB; k++) {
            if (k == c) mine = run;
            run += __ldcg(&g_bsum[t][k]);
        }
        chunk_base = mine;
        if (c == SCAN_NB - 1) g_off[t][N_NODES] = run;
    }
    __syncthreads();

    // intra-block exclusive scan
    int si = s;
#pragma unroll
    for (int d = 1; d < 32; d <<= 1) {
        int n = __shfl_up_sync(0xffffffffu, si, d);
        if (lane >= d) si += n;
    }
    if (lane == 31) ws[wid] = si;
    __syncthreads();
    if (wid == 0) {
        int w = ws[lane];
#pragma unroll
        for (int d = 1; d < 32; d <<= 1) {
            int n = __shfl_up_sync(0xffffffffu, w, d);
            if (lane >= d) w += n;
        }
        ws[lane] = w;
    }
    __syncthreads();
    int run = si - s + (wid ? ws[wid - 1] : 0) + chunk_base;
#pragma unroll
    for (int i = 0; i < 4; i++) {
        int idx = base + tid * 4 + i;
        if (idx < N_NODES) {
            g_off[t][idx] = run;
            pos[idx] = run;
            run += v[i];
        }
    }
}

__global__ void fill3_kernel(const int* __restrict__ e0, const int* __restrict__ e1,
                             const int* __restrict__ e2) {
    int i = blockIdx.x * blockDim.x + threadIdx.x;
    int t = i / NE, j = i % NE;
    const int* e = (t == 0) ? e0 : (t == 1) ? e1 : e2;
    int s = e[j], d = e[NE + j];
    int p = atomicAdd(&pos_ptr(t)[d], 1);
    g_srcs[t][p] = s;
}

// ---------------- schema GCN + dynamic coefficients (1 block, 512 thr) ----------------
__global__ void schema_kernel(const float* __restrict__ schema_x, const int* __restrict__ sei,
                              const float* __restrict__ pre_W, const float* __restrict__ pre_b,
                              const float* __restrict__ gcn_W, const float* __restrict__ gcn_b,
                              const float* __restrict__ coeff_W, const float* __restrict__ coeff_b,
                              float* __restrict__ out_sf, float* __restrict__ out_ori) {
    __shared__ float h [NS][NH];
    __shared__ float xw[NS][NH];
    __shared__ float sf[NS][NH];
    __shared__ float dinv[NS];
    int tid = threadIdx.x;              // 512 = 8*64
    int s = tid / NH, j = tid % NH;

    float acc = pre_b[j];
    for (int i = 0; i < NH; i++) acc += schema_x[s * NH + i] * pre_W[j * NH + i];
    h[s][j] = acc;
    out_ori[s * NH + j] = acc;
    __syncthreads();

    float xacc = 0.f;
    for (int k = 0; k < NH; k++) xacc += h[s][k] * gcn_W[j * NH + k];
    xw[s][j] = xacc;
    if (tid < NS) {
        float d = 1.0f;
        for (int e = 0; e < 24; e++) if (sei[24 + e] == tid) d += 1.0f;
        dinv[tid] = rsqrtf(fmaxf(d, 1e-12f));
    }
    __syncthreads();

    float o = gcn_b[j] + dinv[s] * dinv[s] * xw[s][j];
    for (int e = 0; e < 24; e++) {
        int es = sei[e], ed = sei[24 + e];
        if (ed == s) o += dinv[es] * dinv[s] * xw[es][j];
    }
    o = fmaxf(o, 0.f);
    sf[s][j] = o;
    out_sf[s * NH + j] = o;
    __syncthreads();

    if (tid < 3 * NB_) {
        int t = tid / NB_, i = tid % NB_;
        int ssrc = (t == 1) ? 1 : 0;
        int sdst = (t == 0) ? 1 : 0;
        float c = coeff_b[i];
        for (int k = 0; k < NH; k++) c += sf[ssrc][k] * coeff_W[i * 128 + k];
        for (int k = 0; k < NH; k++) c += sf[sdst][k] * coeff_W[i * 128 + 64 + k];
        g_coeff[t][i] = c;
    }
}

__global__ void buildW_kernel(const float* __restrict__ bases) {
    int id = blockIdx.x * blockDim.x + threadIdx.x;
    if (id >= 2 * NC * NC) return;
    int l = id / (NC * NC);
    int jk = id % (NC * NC);
    int j = jk / NC, k = jk % NC;
    float wab = 0.f, wba = 0.f, waa = 0.f;
#pragma unroll
    for (int i = 0; i < NB_; i++) {
        float b = bases[(size_t)l * NB_ * NC * NC + (size_t)i * NC * NC + jk];
        wab += g_coeff[0][i] * b;
        wba += g_coeff[1][i] * b;
        waa += g_coeff[2][i] * b;
    }
    g_Wab[l][jk] = __float2half(wab);
    g_Wcat[l][j * 256 + k] = __float2half(wba);
    g_Wcat[l][j * 256 + 128 + k] = __float2half(waa);
}

// ---------------- aggregation (fp16 sources, fp32 accum, MLP=8, fp16 out) ----------------
__device__ __forceinline__ void add_u2(uint2 u, float4& a) {
    __half2 h0 = *(__half2*)&u.x, h1 = *(__half2*)&u.y;
    float2 f0 = __half22float2(h0), f1 = __half22float2(h1);
    a.x += f0.x; a.y += f0.y; a.z += f1.x; a.w += f1.y;
}

__device__ __forceinline__ void add_rowh(const __half* __restrict__ p, float4& a) {
    add_u2(*(const uint2*)p, a);
}

__device__ __forceinline__ void acc_range(const __half* __restrict__ xsrc,
                                          const int* __restrict__ srcs,
                                          int beg, int end, int col, float4& out) {
    float4 a0 = make_float4(0, 0, 0, 0), a1 = a0, a2 = a0, a3 = a0;
    int e = beg;
    for (; e + 8 <= end; e += 8) {
        int s0 = srcs[e],     s1 = srcs[e + 1], s2 = srcs[e + 2], s3 = srcs[e + 3];
        int s4 = srcs[e + 4], s5 = srcs[e + 5], s6 = srcs[e + 6], s7 = srcs[e + 7];
        uint2 u0 = *(const uint2*)(xsrc + (size_t)s0 * NC + col);
        uint2 u1 = *(const uint2*)(xsrc + (size_t)s1 * NC + col);
        uint2 u2 = *(const uint2*)(xsrc + (size_t)s2 * NC + col);
        uint2 u3 = *(const uint2*)(xsrc + (size_t)s3 * NC + col);
        uint2 u4 = *(const uint2*)(xsrc + (size_t)s4 * NC + col);
        uint2 u5 = *(const uint2*)(xsrc + (size_t)s5 * NC + col);
        uint2 u6 = *(const uint2*)(xsrc + (size_t)s6 * NC + col);
        uint2 u7 = *(const uint2*)(xsrc + (size_t)s7 * NC + col);
        add_u2(u0, a0); add_u2(u1, a1); add_u2(u2, a2); add_u2(u3, a3);
        add_u2(u4, a0); add_u2(u5, a1); add_u2(u6, a2); add_u2(u7, a3);
    }
    if (e + 4 <= end) {
        int s0 = srcs[e], s1 = srcs[e + 1], s2 = srcs[e + 2], s3 = srcs[e + 3];
        uint2 u0 = *(const uint2*)(xsrc + (size_t)s0 * NC + col);
        uint2 u1 = *(const uint2*)(xsrc + (size_t)s1 * NC + col);
        uint2 u2 = *(const uint2*)(xsrc + (size_t)s2 * NC + col);
        uint2 u3 = *(const uint2*)(xsrc + (size_t)s3 * NC + col);
        add_u2(u0, a0); add_u2(u1, a1); add_u2(u2, a2); add_u2(u3, a3);
        e += 4;
    }
    for (; e < end; e++) add_rowh(xsrc + (size_t)srcs[e] * NC + col, a0);
    float inv = 1.0f / fmaxf((float)(end - beg), 1.0f);
    out.x = (a0.x + a1.x + a2.x + a3.x) * inv;
    out.y = (a0.y + a1.y + a2.y + a3.y) * inv;
    out.z = (a0.z + a1.z + a2.z + a3.z) * inv;
    out.w = (a0.w + a1.w + a2.w + a3.w) * inv;
}

// combined: warps [0,N) -> b-dst (ab edges); warps [N,2N) -> a-dst (ba+aa edges)
__global__ void agg_all_kernel(const __half* __restrict__ ha, const __half* __restrict__ hb,
                               __half* __restrict__ mid_a, __half* __restrict__ mid_b) {
    int g = blockIdx.x * blockDim.x + threadIdx.x;
    int w = g >> 5, lane = g & 31;
    int col = lane * 4;
    if (w < N_NODES) {
        int node = w;
        float4 m;
        acc_range(ha, g_srcs[0], g_off[0][node], g_off[0][node + 1], col, m);
        float4 xd = make_float4(0, 0, 0, 0);
        add_rowh(hb + (size_t)node * NC + col, xd);
        m.x += xd.x; m.y += xd.y; m.z += xd.z; m.w += xd.w;
        uint2 u = make_uint2(pack2(m.x, m.y), pack2(m.z, m.w));
        *(uint2*)(mid_b + (size_t)node * NC + col) = u;
    } else if (w < 2 * N_NODES) {
        int node = w - N_NODES;
        float4 xd = make_float4(0, 0, 0, 0);
        add_rowh(ha + (size_t)node * NC + col, xd);
        float4 m0, m1;
        acc_range(hb, g_srcs[1], g_off[1][node], g_off[1][node + 1], col, m0);
        acc_range(ha, g_srcs[2], g_off[2][node], g_off[2][node + 1], col, m1);
        m0.x += xd.x; m0.y += xd.y; m0.z += xd.z; m0.w += xd.w;
        m1.x += xd.x; m1.y += xd.y; m1.z += xd.z; m1.w += xd.w;
        uint2 u0 = make_uint2(pack2(m0.x, m0.y), pack2(m0.z, m0.w));
        uint2 u1 = make_uint2(pack2(m1.x, m1.y), pack2(m1.z, m1.w));
        *(uint2*)(mid_a + (size_t)node * 256 + col) = u0;
        *(uint2*)(mid_a + (size_t)node * 256 + 128 + col) = u1;
    }
}

// ---------------- fp16 GEMM (m16n8k16, fp32 accum) + bias + LayerNorm + ReLU ----------------
#define APITCH_H 40
#define OPITCH 132

// A, W fp16. OUTH=0: fp32 output to `out`; OUTH=1: fp16 output to `hout`.
template <int K, int OUTH>
__global__ void __launch_bounds__(256)
gemm_ln_kernel(const __half* __restrict__ A, const __half* __restrict__ W,
               const float* __restrict__ b1, const float* __restrict__ b2,
               const float* __restrict__ lw, const float* __restrict__ lb,
               float* __restrict__ out, __half* __restrict__ hout, int M) {
    extern __shared__ float buf[];           // 16896 floats (Ot [128][132] dominates)
    __half* At = (__half*)buf;               // [128][40] halves
    __half* Wt = At + 128 * APITCH_H;        // [128][40] halves
    __shared__ float sb[3][NC];

    int tid = threadIdx.x;
    int lane = tid & 31, wid = tid >> 5;
    int warp_m = wid >> 2, warp_n = wid & 3; // 2 x 4 warps
    int gid = lane >> 2, tig = lane & 3;
    int row0 = blockIdx.x * 128;

    if (tid < NC) {
        float c = b1[tid];
        if (b2) c += b2[tid];
        sb[0][tid] = c;
        sb[1][tid] = lw[tid];
        sb[2][tid] = lb[tid];
    }

    float acc[4][4][4];
#pragma unroll
    for (int i = 0; i < 4; i++)
#pragma unroll
        for (int j = 0; j < 4; j++)
#pragma unroll
            for (int c = 0; c < 4; c++) acc[i][j][c] = 0.f;

    for (int kc = 0; kc < K; kc += 32) {
#pragma unroll
        for (int it = 0; it < 4; it++) {
            int idx = tid + it * 256;        // 0..1023; r=row, seg=4-half group
            int r = idx >> 3, seg = idx & 7;
            uint2 va = make_uint2(0, 0);
            if (row0 + r < M)
                va = *(const uint2*)(A + (size_t)(row0 + r) * K + kc + seg * 4);
            *(uint2*)(At + r * APITCH_H + seg * 4) = va;
            uint2 vw = *(const uint2*)(W + (size_t)r * K + kc + seg * 4);
            *(uint2*)(Wt + r * APITCH_H + seg * 4) = vw;
        }
        __syncthreads();
#pragma unroll
        for (int ks = 0; ks < 2; ks++) {
            int k = ks * 16;
            unsigned bfr[4][2];
#pragma unroll
            for (int j = 0; j < 4; j++) {
                int n0 = warp_n * 32 + j * 8;
                bfr[j][0] = *(const unsigned*)(Wt + (n0 + gid) * APITCH_H + k + 2 * tig);
                bfr[j][1] = *(const unsigned*)(Wt + (n0 + gid) * APITCH_H + k + 2 * tig + 8);
            }
#pragma unroll
            for (int i = 0; i < 4; i++) {
                int m0 = warp_m * 64 + i * 16;
                unsigned a0 = *(const unsigned*)(At + (m0 + gid) * APITCH_H + k + 2 * tig);
                unsigned a1 = *(const unsigned*)(At + (m0 + gid + 8) * APITCH_H + k + 2 * tig);
                unsigned a2 = *(const unsigned*)(At + (m0 + gid) * APITCH_H + k + 2 * tig + 8);
                unsigned a3 = *(const unsigned*)(At + (m0 + gid + 8) * APITCH_H + k + 2 * tig + 8);
#pragma unroll
                for (int j = 0; j < 4; j++) {
                    asm volatile(
                        "mma.sync.aligned.m16n8k16.row.col.f32.f16.f16.f32 "
                        "{%0,%1,%2,%3}, {%4,%5,%6,%7}, {%8,%9}, {%0,%1,%2,%3};\n"
                        : "+f"(acc[i][j][0]), "+f"(acc[i][j][1]),
                          "+f"(acc[i][j][2]), "+f"(acc[i][j][3])
                        : "r"(a0), "r"(a1), "r"(a2), "r"(a3),
                          "r"(bfr[j][0]), "r"(bfr[j][1]));
                }
            }
        }
        __syncthreads();
    }

    float* Ot = buf;                         // [128][132] fp32, aliases tiles
#pragma unroll
    for (int i = 0; i < 4; i++) {
        int m0 = warp_m * 64 + i * 16;
#pragma unroll
        for (int j = 0; j < 4; j++) {
            int n0 = warp_n * 32 + j * 8 + 2 * tig;
            Ot[(m0 + gid) * OPITCH + n0]         = acc[i][j][0];
            Ot[(m0 + gid) * OPITCH + n0 + 1]     = acc[i][j][1];
            Ot[(m0 + gid + 8) * OPITCH + n0]     = acc[i][j][2];
            Ot[(m0 + gid + 8) * OPITCH + n0 + 1] = acc[i][j][3];
        }
    }
    __syncthreads();

    int col = lane * 4;
    for (int rr = 0; rr < 16; rr++) {
        int r = wid * 16 + rr;
        int grow = row0 + r;
        if (grow >= M) break;
        float4 v = *(const float4*)&Ot[r * OPITCH + col];
        v.x += sb[0][col];     v.y += sb[0][col + 1];
        v.z += sb[0][col + 2]; v.w += sb[0][col + 3];
        float s = v.x + v.y + v.z + v.w;
#pragma unroll
        for (int o = 16; o > 0; o >>= 1) s += __shfl_xor_sync(0xffffffffu, s, o);
        float mu = s * (1.0f / NC);
        float dx = v.x - mu, dy = v.y - mu, dz = v.z - mu, dw = v.w - mu;
        float q = dx * dx + dy * dy + dz * dz + dw * dw;
#pragma unroll
        for (int o = 16; o > 0; o >>= 1) q += __shfl_xor_sync(0xffffffffu, q, o);
        float rs = rsqrtf(q * (1.0f / NC) + LN_EPS);
        float4 y;
        y.x = fmaxf(dx * rs * sb[1][col]     + sb[2][col],     0.f);
        y.y = fmaxf(dy * rs * sb[1][col + 1] + sb[2][col + 1], 0.f);
        y.z = fmaxf(dz * rs * sb[1][col + 2] + sb[2][col + 2], 0.f);
        y.w = fmaxf(dw * rs * sb[1][col + 3] + sb[2][col + 3], 0.f);
        if (OUTH) {
            uint2 u = make_uint2(pack2(y.x, y.y), pack2(y.z, y.w));
            *(uint2*)(hout + (size_t)grow * NC + col) = u;
        } else {
            *(float4*)(out + (size_t)grow * NC + col) = y;
        }
    }
}

// ---------------- launch ----------------
extern "C" void kernel_launch(void* const* d_in, const int* in_sizes, int n_in,
                              void* d_out, int out_size) {
    (void)in_sizes; (void)n_in; (void)out_size;
    const float* x_a      = (const float*)d_in[0];
    const float* x_b      = (const float*)d_in[1];
    const float* schema_x = (const float*)d_in[2];
    const int*   e_ab     = (const int*)d_in[3];
    const int*   e_ba     = (const int*)d_in[4];
    const int*   e_aa     = (const int*)d_in[5];
    const int*   sei      = (const int*)d_in[6];
    const float* pre_W    = (const float*)d_in[7];
    const float* pre_b    = (const float*)d_in[8];
    const float* gcn_W    = (const float*)d_in[9];
    const float* gcn_b    = (const float*)d_in[10];
    const float* coeff_W  = (const float*)d_in[11];
    const float* coeff_b  = (const float*)d_in[12];
    const float* bases    = (const float*)d_in[13];
    const float* sage_bias= (const float*)d_in[14];
    const float* ln_w     = (const float*)d_in[15];
    const float* ln_b     = (const float*)d_in[16];

    float* out = (float*)d_out;
    float* out_xa  = out;
    float* out_xb  = out + (size_t)N_NODES * NC;
    float* out_sf  = out + (size_t)2 * N_NODES * NC;
    float* out_ori = out_sf + NS * NH;

    int* p_zero;
    __half *p_ha, *p_hb, *p_mid_a, *p_mid_b, *p_Wab, *p_Wcat;
    cudaGetSymbolAddress((void**)&p_zero,  g_zero_base);
    cudaGetSymbolAddress((void**)&p_mid_a, g_mid_a);
    cudaGetSymbolAddress((void**)&p_mid_b, g_mid_b);
    cudaGetSymbolAddress((void**)&p_ha,    g_ha);
    cudaGetSymbolAddress((void**)&p_hb,    g_hb);
    cudaGetSymbolAddress((void**)&p_Wab,   g_Wab);
    cudaGetSymbolAddress((void**)&p_Wcat,  g_Wcat);

    const int SMEM_GEMM = 16896 * sizeof(float);
    cudaFuncSetAttribute(gemm_ln_kernel<256, 0>,
                         cudaFuncAttributeMaxDynamicSharedMemorySize, SMEM_GEMM);
    cudaFuncSetAttribute(gemm_ln_kernel<128, 0>,
                         cudaFuncAttributeMaxDynamicSharedMemorySize, SMEM_GEMM);
    cudaFuncSetAttribute(gemm_ln_kernel<256, 1>,
                         cudaFuncAttributeMaxDynamicSharedMemorySize, SMEM_GEMM);
    cudaFuncSetAttribute(gemm_ln_kernel<128, 1>,
                         cudaFuncAttributeMaxDynamicSharedMemorySize, SMEM_GEMM);

    // ---- CSR build + fp16 conversion ----
    cudaMemsetAsync(p_zero, 0, sizeof(int) * (3 * N_NODES + 64));
    hist_tohalf_kernel<<<HIST_BLOCKS + TOHALF_BLOCKS, 256>>>(e_ab, e_ba, e_aa, x_a, x_b);
    scan_fused_kernel<<<3 * SCAN_NB, 1024>>>();
    fill3_kernel<<<3 * NE / 256, 256>>>(e_ab, e_ba, e_aa);

    // ---- schema + dynamic weights ----
    schema_kernel<<<1, 512>>>(schema_x, sei, pre_W, pre_b, gcn_W, gcn_b,
                              coeff_W, coeff_b, out_sf, out_ori);
    buildW_kernel<<<(2 * NC * NC + 255) / 256, 256>>>(bases);

    const int AGG_GRID  = (2 * N_NODES * 32 + 255) / 256;
    const int GEMM_GRID = (N_NODES + 127) / 128;

    // ---- layer 0 (outputs only needed as fp16 for layer 1) ----
    agg_all_kernel<<<AGG_GRID, 256>>>(p_ha, p_hb, p_mid_a, p_mid_b);
    gemm_ln_kernel<256, 1><<<GEMM_GRID, 256, SMEM_GEMM>>>(
        p_mid_a, p_Wcat, sage_bias + 1 * NC, sage_bias + 2 * NC,
        ln_w + 0 * NC, ln_b + 0 * NC, nullptr, p_ha, N_NODES);
    gemm_ln_kernel<128, 1><<<GEMM_GRID, 256, SMEM_GEMM>>>(
        p_mid_b, p_Wab, sage_bias + 0 * NC, nullptr,
        ln_w + 1 * NC, ln_b + 1 * NC, nullptr, p_hb, N_NODES);

    // ---- layer 1 (fp32 outputs to d_out) ----
    agg_all_kernel<<<AGG_GRID, 256>>>(p_ha, p_hb, p_mid_a, p_mid_b);
    gemm_ln_kernel<256, 0><<<GEMM_GRID, 256, SMEM_GEMM>>>(
        p_mid_a, p_Wcat + NC * 256, sage_bias + 4 * NC, sage_bias + 5 * NC,
        ln_w + 2 * NC, ln_b + 2 * NC, out_xa, nullptr, N_NODES);
    gemm_ln_kernel<128, 0><<<GEMM_GRID, 256, SMEM_GEMM>>>(
        p_mid_b, p_Wab + NC * NC, sage_bias + 3 * NC, nullptr,
        ln_w + 3 * NC, ln_b + 3 * NC, out_xb, nullptr, N_NODES);
}

// round 17
// speedup vs baseline: 1.9621x; 1.0680x over previous
#include <cuda_runtime.h>
#include <cuda_fp16.h>
#include <cstddef>

#define N_NODES 50000
#define NC 128
#define NE 800000
#define NS 8
#define NH 64
#define NB_ 8
#define LN_EPS 1e-5f
#define SCAN_NB 13
#define SCAN_CHUNK 4096
#define HIST_BLOCKS (3 * NE / 256)
#define TOHALF_BLOCKS (2 * N_NODES * NC / 8 / 256)

// ---------------- scratch (device globals; no allocation) ----------------
// g_zero_base = [ pos(3*N) | flags(64) ]  — zeroed by one memset per launch
__device__ int    g_zero_base[3 * N_NODES + 64];
__device__ int    g_off [3][N_NODES + 1];
__device__ int    g_bsum[3][SCAN_NB];
__device__ int    g_srcs[3][NE];
__device__ __half g_mid_a[(size_t)N_NODES * 256];
__device__ __half g_mid_b[(size_t)N_NODES * NC];
__device__ __half g_ha[(size_t)N_NODES * NC];
__device__ __half g_hb[(size_t)N_NODES * NC];
__device__ __half g_Wab [2][NC * NC];
__device__ __half g_Wcat[2][NC * 256];     // [j][0:128]=W_ba  [j][128:256]=W_aa
__device__ float  g_coeff[3][NB_];         // 0: ab, 1: ba, 2: aa

__device__ __forceinline__ int* pos_ptr(int t) { return g_zero_base + t * N_NODES; }
#define FLAGS (g_zero_base + 3 * N_NODES)

__device__ __forceinline__ unsigned pack2(float a, float b) {
    __half2 h = __floats2half2_rn(a, b);
    return *(unsigned*)&h;
}

// ---------------- hist + fp16 conversion fused ----------------
__global__ void hist_tohalf_kernel(const int* __restrict__ e0, const int* __restrict__ e1,
                                   const int* __restrict__ e2,
                                   const float* __restrict__ xa, const float* __restrict__ xb) {
    if (blockIdx.x < HIST_BLOCKS) {
        int i = blockIdx.x * blockDim.x + threadIdx.x;      // covers exactly 3*NE
        int t = i / NE, j = i % NE;
        const int* e = (t == 0) ? e0 : (t == 1) ? e1 : e2;
        atomicAdd(&pos_ptr(t)[e[NE + j]], 1);
    } else {
        int i = (blockIdx.x - HIST_BLOCKS) * blockDim.x + threadIdx.x;  // 8 floats each
        const size_t TOT = (size_t)N_NODES * NC;
        size_t base = (size_t)i * 8;
        const float* src;
        __half* dst;
        if (base < TOT) { src = xa + base; dst = g_ha + base; }
        else            { src = xb + (base - TOT); dst = g_hb + (base - TOT); }
        float4 v0 = *(const float4*)src;
        float4 v1 = *(const float4*)(src + 4);
        uint4 u = make_uint4(pack2(v0.x, v0.y), pack2(v0.z, v0.w),
                             pack2(v1.x, v1.y), pack2(v1.z, v1.w));
        *(uint4*)dst = u;
    }
}

// ---------------- fused CSR scan: one kernel, 39 resident blocks ----------------
__global__ void scan_fused_kernel() {       // grid = 3*SCAN_NB, block = 1024
    int t = blockIdx.x / SCAN_NB, c = blockIdx.x % SCAN_NB;
    int base = c * SCAN_CHUNK;
    int tid = threadIdx.x, lane = tid & 31, wid = tid >> 5;
    int* pos = pos_ptr(t);

    int v[4], s = 0;
#pragma unroll
    for (int i = 0; i < 4; i++) {
        int idx = base + tid * 4 + i;
        v[i] = (idx < N_NODES) ? pos[idx] : 0;
        s += v[i];
    }

    // block total
    int r = s;
#pragma unroll
    for (int o = 16; o > 0; o >>= 1) r += __shfl_xor_sync(0xffffffffu, r, o);
    __shared__ int ws[32];
    if (lane == 0) ws[wid] = r;
    __syncthreads();

    __shared__ int chunk_base;
    if (tid == 0) {
        int tot = 0;
#pragma unroll
        for (int w = 0; w < 32; w++) tot += ws[w];
        g_bsum[t][c] = tot;
        __threadfence();
        atomicExch(&FLAGS[t * 16 + c], 1);
        // wait for all chunks of this edge type
        for (int k = 0; k < SCAN_NB; k++) {
            volatile int* f = &FLAGS[t * 16 + k];
            while (*f == 0) { }
        }
        __threadfence();
        int run = 0, mine = 0;
        for (int k = 0; k < SCAN_NB; k++) {
            if (k == c) mine = run;
            run += __ldcg(&g_bsum[t][k]);
        }
        chunk_base = mine;
        if (c == SCAN_NB - 1) g_off[t][N_NODES] = run;
    }
    __syncthreads();

    // intra-block exclusive scan
    int si = s;
#pragma unroll
    for (int d = 1; d < 32; d <<= 1) {
        int n = __shfl_up_sync(0xffffffffu, si, d);
        if (lane >= d) si += n;
    }
    if (lane == 31) ws[wid] = si;
    __syncthreads();
    if (wid == 0) {
        int w = ws[lane];
#pragma unroll
        for (int d = 1; d < 32; d <<= 1) {
            int n = __shfl_up_sync(0xffffffffu, w, d);
            if (lane >= d) w += n;
        }
        ws[lane] = w;
    }
    __syncthreads();
    int run = si - s + (wid ? ws[wid - 1] : 0) + chunk_base;
#pragma unroll
    for (int i = 0; i < 4; i++) {
        int idx = base + tid * 4 + i;
        if (idx < N_NODES) {
            g_off[t][idx] = run;
            pos[idx] = run;
            run += v[i];
        }
    }
}

__global__ void fill3_kernel(const int* __restrict__ e0, const int* __restrict__ e1,
                             const int* __restrict__ e2) {
    int i = blockIdx.x * blockDim.x + threadIdx.x;
    int t = i / NE, j = i % NE;
    const int* e = (t == 0) ? e0 : (t == 1) ? e1 : e2;
    int s = e[j], d = e[NE + j];
    int p = atomicAdd(&pos_ptr(t)[d], 1);
    g_srcs[t][p] = s;
}

// ---------------- schema GCN + dynamic coefficients (1 block, 512 thr) ----------------
// All small matrices staged to shared memory with coalesced loads; 64-wide
// matrices padded to 65 so j-varying inner-loop reads are bank-conflict-free.
__global__ void schema_kernel(const float* __restrict__ schema_x, const int* __restrict__ sei,
                              const float* __restrict__ pre_W, const float* __restrict__ pre_b,
                              const float* __restrict__ gcn_W, const float* __restrict__ gcn_b,
                              const float* __restrict__ coeff_W, const float* __restrict__ coeff_b,
                              float* __restrict__ out_sf, float* __restrict__ out_ori) {
    __shared__ float sxs[NS][NH];
    __shared__ float pWs[NH][NH + 1];
    __shared__ float gWs[NH][NH + 1];
    __shared__ float cWs[NB_][2 * NH];
    __shared__ int   seis[48];
    __shared__ float h [NS][NH];
    __shared__ float xw[NS][NH];
    __shared__ float sf[NS][NH];
    __shared__ float dinv[NS];
    int tid = threadIdx.x;              // 512 = 8*64

    // stage (coalesced global reads)
    for (int i = tid; i < NS * NH; i += 512)     sxs[i / NH][i % NH] = schema_x[i];
    for (int i = tid; i < NH * NH; i += 512)     pWs[i / NH][i % NH] = pre_W[i];
    for (int i = tid; i < NH * NH; i += 512)     gWs[i / NH][i % NH] = gcn_W[i];
    for (int i = tid; i < NB_ * 2 * NH; i += 512) cWs[i / (2 * NH)][i % (2 * NH)] = coeff_W[i];
    if (tid < 48) seis[tid] = sei[tid];
    __syncthreads();

    int s = tid / NH, j = tid % NH;

    float acc = pre_b[j];
#pragma unroll 8
    for (int i = 0; i < NH; i++) acc += sxs[s][i] * pWs[j][i];
    h[s][j] = acc;
    out_ori[s * NH + j] = acc;
    __syncthreads();

    float xacc = 0.f;
#pragma unroll 8
    for (int k = 0; k < NH; k++) xacc += h[s][k] * gWs[j][k];
    xw[s][j] = xacc;
    if (tid < NS) {
        float d = 1.0f;                  // self loop
#pragma unroll
        for (int e = 0; e < 24; e++) if (seis[24 + e] == tid) d += 1.0f;
        dinv[tid] = rsqrtf(fmaxf(d, 1e-12f));
    }
    __syncthreads();

    float o = gcn_b[j] + dinv[s] * dinv[s] * xw[s][j];
#pragma unroll
    for (int e = 0; e < 24; e++) {
        int es = seis[e], ed = seis[24 + e];
        if (ed == s) o += dinv[es] * dinv[s] * xw[es][j];
    }
    o = fmaxf(o, 0.f);
    sf[s][j] = o;
    out_sf[s * NH + j] = o;
    __syncthreads();

    if (tid < 3 * NB_) {
        int t = tid / NB_, i = tid % NB_;
        int ssrc = (t == 1) ? 1 : 0;     // ab:(0,1) ba:(1,0) aa:(0,0)
        int sdst = (t == 0) ? 1 : 0;
        float c = coeff_b[i];
#pragma unroll 8
        for (int k = 0; k < NH; k++) c += sf[ssrc][k] * cWs[i][k];
#pragma unroll 8
        for (int k = 0; k < NH; k++) c += sf[sdst][k] * cWs[i][64 + k];
        g_coeff[t][i] = c;
    }
}

__global__ void buildW_kernel(const float* __restrict__ bases) {
    int id = blockIdx.x * blockDim.x + threadIdx.x;
    if (id >= 2 * NC * NC) return;
    int l = id / (NC * NC);
    int jk = id % (NC * NC);
    int j = jk / NC, k = jk % NC;
    float wab = 0.f, wba = 0.f, waa = 0.f;
#pragma unroll
    for (int i = 0; i < NB_; i++) {
        float b = bases[(size_t)l * NB_ * NC * NC + (size_t)i * NC * NC + jk];
        wab += g_coeff[0][i] * b;
        wba += g_coeff[1][i] * b;
        waa += g_coeff[2][i] * b;
    }
    g_Wab[l][jk] = __float2half(wab);
    g_Wcat[l][j * 256 + k] = __float2half(wba);
    g_Wcat[l][j * 256 + 128 + k] = __float2half(waa);
}

// ---------------- aggregation (fp16 sources, fp32 accum, MLP=8, fp16 out) ----------------
__device__ __forceinline__ void add_u2(uint2 u, float4& a) {
    __half2 h0 = *(__half2*)&u.x, h1 = *(__half2*)&u.y;
    float2 f0 = __half22float2(h0), f1 = __half22float2(h1);
    a.x += f0.x; a.y += f0.y; a.z += f1.x; a.w += f1.y;
}

__device__ __forceinline__ void add_rowh(const __half* __restrict__ p, float4& a) {
    add_u2(*(const uint2*)p, a);
}

__device__ __forceinline__ void acc_range(const __half* __restrict__ xsrc,
                                          const int* __restrict__ srcs,
                                          int beg, int end, int col, float4& out) {
    float4 a0 = make_float4(0, 0, 0, 0), a1 = a0, a2 = a0, a3 = a0;
    int e = beg;
    for (; e + 8 <= end; e += 8) {
        int s0 = srcs[e],     s1 = srcs[e + 1], s2 = srcs[e + 2], s3 = srcs[e + 3];
        int s4 = srcs[e + 4], s5 = srcs[e + 5], s6 = srcs[e + 6], s7 = srcs[e + 7];
        uint2 u0 = *(const uint2*)(xsrc + (size_t)s0 * NC + col);
        uint2 u1 = *(const uint2*)(xsrc + (size_t)s1 * NC + col);
        uint2 u2 = *(const uint2*)(xsrc + (size_t)s2 * NC + col);
        uint2 u3 = *(const uint2*)(xsrc + (size_t)s3 * NC + col);
        uint2 u4 = *(const uint2*)(xsrc + (size_t)s4 * NC + col);
        uint2 u5 = *(const uint2*)(xsrc + (size_t)s5 * NC + col);
        uint2 u6 = *(const uint2*)(xsrc + (size_t)s6 * NC + col);
        uint2 u7 = *(const uint2*)(xsrc + (size_t)s7 * NC + col);
        add_u2(u0, a0); add_u2(u1, a1); add_u2(u2, a2); add_u2(u3, a3);
        add_u2(u4, a0); add_u2(u5, a1); add_u2(u6, a2); add_u2(u7, a3);
    }
    if (e + 4 <= end) {
        int s0 = srcs[e], s1 = srcs[e + 1], s2 = srcs[e + 2], s3 = srcs[e + 3];
        uint2 u0 = *(const uint2*)(xsrc + (size_t)s0 * NC + col);
        uint2 u1 = *(const uint2*)(xsrc + (size_t)s1 * NC + col);
        uint2 u2 = *(const uint2*)(xsrc + (size_t)s2 * NC + col);
        uint2 u3 = *(const uint2*)(xsrc + (size_t)s3 * NC + col);
        add_u2(u0, a0); add_u2(u1, a1); add_u2(u2, a2); add_u2(u3, a3);
        e += 4;
    }
    for (; e < end; e++) add_rowh(xsrc + (size_t)srcs[e] * NC + col, a0);
    float inv = 1.0f / fmaxf((float)(end - beg), 1.0f);
    out.x = (a0.x + a1.x + a2.x + a3.x) * inv;
    out.y = (a0.y + a1.y + a2.y + a3.y) * inv;
    out.z = (a0.z + a1.z + a2.z + a3.z) * inv;
    out.w = (a0.w + a1.w + a2.w + a3.w) * inv;
}

// combined: warps [0,N) -> b-dst (ab edges); warps [N,2N) -> a-dst (ba+aa edges)
__global__ void agg_all_kernel(const __half* __restrict__ ha, const __half* __restrict__ hb,
                               __half* __restrict__ mid_a, __half* __restrict__ mid_b) {
    int g = blockIdx.x * blockDim.x + threadIdx.x;
    int w = g >> 5, lane = g & 31;
    int col = lane * 4;
    if (w < N_NODES) {
        int node = w;
        float4 m;
        acc_range(ha, g_srcs[0], g_off[0][node], g_off[0][node + 1], col, m);
        float4 xd = make_float4(0, 0, 0, 0);
        add_rowh(hb + (size_t)node * NC + col, xd);
        m.x += xd.x; m.y += xd.y; m.z += xd.z; m.w += xd.w;
        uint2 u = make_uint2(pack2(m.x, m.y), pack2(m.z, m.w));
        *(uint2*)(mid_b + (size_t)node * NC + col) = u;
    } else if (w < 2 * N_NODES) {
        int node = w - N_NODES;
        float4 xd = make_float4(0, 0, 0, 0);
        add_rowh(ha + (size_t)node * NC + col, xd);
        float4 m0, m1;
        acc_range(hb, g_srcs[1], g_off[1][node], g_off[1][node + 1], col, m0);
        acc_range(ha, g_srcs[2], g_off[2][node], g_off[2][node + 1], col, m1);
        m0.x += xd.x; m0.y += xd.y; m0.z += xd.z; m0.w += xd.w;
        m1.x += xd.x; m1.y += xd.y; m1.z += xd.z; m1.w += xd.w;
        uint2 u0 = make_uint2(pack2(m0.x, m0.y), pack2(m0.z, m0.w));
        uint2 u1 = make_uint2(pack2(m1.x, m1.y), pack2(m1.z, m1.w));
        *(uint2*)(mid_a + (size_t)node * 256 + col) = u0;
        *(uint2*)(mid_a + (size_t)node * 256 + 128 + col) = u1;
    }
}

// ---------------- fp16 GEMM (m16n8k16, fp32 accum) + bias + LayerNorm + ReLU ----------------
#define APITCH_H 40
#define OPITCH 132

// A, W fp16. OUTH=0: fp32 output to `out`; OUTH=1: fp16 output to `hout`.
template <int K, int OUTH>
__global__ void __launch_bounds__(256)
gemm_ln_kernel(const __half* __restrict__ A, const __half* __restrict__ W,
               const float* __restrict__ b1, const float* __restrict__ b2,
               const float* __restrict__ lw, const float* __restrict__ lb,
               float* __restrict__ out, __half* __restrict__ hout, int M) {
    extern __shared__ float buf[];           // 16896 floats (Ot [128][132] dominates)
    __half* At = (__half*)buf;               // [128][40] halves
    __half* Wt = At + 128 * APITCH_H;        // [128][40] halves
    __shared__ float sb[3][NC];

    int tid = threadIdx.x;
    int lane = tid & 31, wid = tid >> 5;
    int warp_m = wid >> 2, warp_n = wid & 3; // 2 x 4 warps
    int gid = lane >> 2, tig = lane & 3;
    int row0 = blockIdx.x * 128;

    if (tid < NC) {
        float c = b1[tid];
        if (b2) c += b2[tid];
        sb[0][tid] = c;
        sb[1][tid] = lw[tid];
        sb[2][tid] = lb[tid];
    }

    float acc[4][4][4];
#pragma unroll
    for (int i = 0; i < 4; i++)
#pragma unroll
        for (int j = 0; j < 4; j++)
#pragma unroll
            for (int c = 0; c < 4; c++) acc[i][j][c] = 0.f;

    for (int kc = 0; kc < K; kc += 32) {
#pragma unroll
        for (int it = 0; it < 4; it++) {
            int idx = tid + it * 256;        // 0..1023; r=row, seg=4-half group
            int r = idx >> 3, seg = idx & 7;
            uint2 va = make_uint2(0, 0);
            if (row0 + r < M)
                va = *(const uint2*)(A + (size_t)(row0 + r) * K + kc + seg * 4);
            *(uint2*)(At + r * APITCH_H + seg * 4) = va;
            uint2 vw = *(const uint2*)(W + (size_t)r * K + kc + seg * 4);
            *(uint2*)(Wt + r * APITCH_H + seg * 4) = vw;
        }
        __syncthreads();
#pragma unroll
        for (int ks = 0; ks < 2; ks++) {
            int k = ks * 16;
            unsigned bfr[4][2];
#pragma unroll
            for (int j = 0; j < 4; j++) {
                int n0 = warp_n * 32 + j * 8;
                bfr[j][0] = *(const unsigned*)(Wt + (n0 + gid) * APITCH_H + k + 2 * tig);
                bfr[j][1] = *(const unsigned*)(Wt + (n0 + gid) * APITCH_H + k + 2 * tig + 8);
            }
#pragma unroll
            for (int i = 0; i < 4; i++) {
                int m0 = warp_m * 64 + i * 16;
                unsigned a0 = *(const unsigned*)(At + (m0 + gid) * APITCH_H + k + 2 * tig);
                unsigned a1 = *(const unsigned*)(At + (m0 + gid + 8) * APITCH_H + k + 2 * tig);
                unsigned a2 = *(const unsigned*)(At + (m0 + gid) * APITCH_H + k + 2 * tig + 8);
                unsigned a3 = *(const unsigned*)(At + (m0 + gid + 8) * APITCH_H + k + 2 * tig + 8);
#pragma unroll
                for (int j = 0; j < 4; j++) {
                    asm volatile(
                        "mma.sync.aligned.m16n8k16.row.col.f32.f16.f16.f32 "
                        "{%0,%1,%2,%3}, {%4,%5,%6,%7}, {%8,%9}, {%0,%1,%2,%3};\n"
                        : "+f"(acc[i][j][0]), "+f"(acc[i][j][1]),
                          "+f"(acc[i][j][2]), "+f"(acc[i][j][3])
                        : "r"(a0), "r"(a1), "r"(a2), "r"(a3),
                          "r"(bfr[j][0]), "r"(bfr[j][1]));
                }
            }
        }
        __syncthreads();
    }

    float* Ot = buf;                         // [128][132] fp32, aliases tiles
#pragma unroll
    for (int i = 0; i < 4; i++) {
        int m0 = warp_m * 64 + i * 16;
#pragma unroll
        for (int j = 0; j < 4; j++) {
            int n0 = warp_n * 32 + j * 8 + 2 * tig;
            Ot[(m0 + gid) * OPITCH + n0]         = acc[i][j][0];
            Ot[(m0 + gid) * OPITCH + n0 + 1]     = acc[i][j][1];
            Ot[(m0 + gid + 8) * OPITCH + n0]     = acc[i][j][2];
            Ot[(m0 + gid + 8) * OPITCH + n0 + 1] = acc[i][j][3];
        }
    }
    __syncthreads();

    int col = lane * 4;
    for (int rr = 0; rr < 16; rr++) {
        int r = wid * 16 + rr;
        int grow = row0 + r;
        if (grow >= M) break;
        float4 v = *(const float4*)&Ot[r * OPITCH + col];
        v.x += sb[0][col];     v.y += sb[0][col + 1];
        v.z += sb[0][col + 2]; v.w += sb[0][col + 3];
        float s = v.x + v.y + v.z + v.w;
#pragma unroll
        for (int o = 16; o > 0; o >>= 1) s += __shfl_xor_sync(0xffffffffu, s, o);
        float mu = s * (1.0f / NC);
        float dx = v.x - mu, dy = v.y - mu, dz = v.z - mu, dw = v.w - mu;
        float q = dx * dx + dy * dy + dz * dz + dw * dw;
#pragma unroll
        for (int o = 16; o > 0; o >>= 1) q += __shfl_xor_sync(0xffffffffu, q, o);
        float rs = rsqrtf(q * (1.0f / NC) + LN_EPS);
        float4 y;
        y.x = fmaxf(dx * rs * sb[1][col]     + sb[2][col],     0.f);
        y.y = fmaxf(dy * rs * sb[1][col + 1] + sb[2][col + 1], 0.f);
        y.z = fmaxf(dz * rs * sb[1][col + 2] + sb[2][col + 2], 0.f);
        y.w = fmaxf(dw * rs * sb[1][col + 3] + sb[2][col + 3], 0.f);
        if (OUTH) {
            uint2 u = make_uint2(pack2(y.x, y.y), pack2(y.z, y.w));
            *(uint2*)(hout + (size_t)grow * NC + col) = u;
        } else {
            *(float4*)(out + (size_t)grow * NC + col) = y;
        }
    }
}

// ---------------- launch ----------------
extern "C" void kernel_launch(void* const* d_in, const int* in_sizes, int n_in,
                              void* d_out, int out_size) {
    (void)in_sizes; (void)n_in; (void)out_size;
    const float* x_a      = (const float*)d_in[0];
    const float* x_b      = (const float*)d_in[1];
    const float* schema_x = (const float*)d_in[2];
    const int*   e_ab     = (const int*)d_in[3];
    const int*   e_ba     = (const int*)d_in[4];
    const int*   e_aa     = (const int*)d_in[5];
    const int*   sei      = (const int*)d_in[6];
    const float* pre_W    = (const float*)d_in[7];
    const float* pre_b    = (const float*)d_in[8];
    const float* gcn_W    = (const float*)d_in[9];
    const float* gcn_b    = (const float*)d_in[10];
    const float* coeff_W  = (const float*)d_in[11];
    const float* coeff_b  = (const float*)d_in[12];
    const float* bases    = (const float*)d_in[13];
    const float* sage_bias= (const float*)d_in[14];
    const float* ln_w     = (const float*)d_in[15];
    const float* ln_b     = (const float*)d_in[16];

    float* out = (float*)d_out;
    float* out_xa  = out;
    float* out_xb  = out + (size_t)N_NODES * NC;
    float* out_sf  = out + (size_t)2 * N_NODES * NC;
    float* out_ori = out_sf + NS * NH;

    int* p_zero;
    __half *p_ha, *p_hb, *p_mid_a, *p_mid_b, *p_Wab, *p_Wcat;
    cudaGetSymbolAddress((void**)&p_zero,  g_zero_base);
    cudaGetSymbolAddress((void**)&p_mid_a, g_mid_a);
    cudaGetSymbolAddress((void**)&p_mid_b, g_mid_b);
    cudaGetSymbolAddress((void**)&p_ha,    g_ha);
    cudaGetSymbolAddress((void**)&p_hb,    g_hb);
    cudaGetSymbolAddress((void**)&p_Wab,   g_Wab);
    cudaGetSymbolAddress((void**)&p_Wcat,  g_Wcat);

    const int SMEM_GEMM = 16896 * sizeof(float);
    cudaFuncSetAttribute(gemm_ln_kernel<256, 0>,
                         cudaFuncAttributeMaxDynamicSharedMemorySize, SMEM_GEMM);
    cudaFuncSetAttribute(gemm_ln_kernel<128, 0>,
                         cudaFuncAttributeMaxDynamicSharedMemorySize, SMEM_GEMM);
    cudaFuncSetAttribute(gemm_ln_kernel<256, 1>,
                         cudaFuncAttributeMaxDynamicSharedMemorySize, SMEM_GEMM);
    cudaFuncSetAttribute(gemm_ln_kernel<128, 1>,
                         cudaFuncAttributeMaxDynamicSharedMemorySize, SMEM_GEMM);

    // ---- CSR build + fp16 conversion ----
    cudaMemsetAsync(p_zero, 0, sizeof(int) * (3 * N_NODES + 64));
    hist_tohalf_kernel<<<HIST_BLOCKS + TOHALF_BLOCKS, 256>>>(e_ab, e_ba, e_aa, x_a, x_b);
    scan_fused_kernel<<<3 * SCAN_NB, 1024>>>();
    fill3_kernel<<<3 * NE / 256, 256>>>(e_ab, e_ba, e_aa);

    // ---- schema + dynamic weights ----
    schema_kernel<<<1, 512>>>(schema_x, sei, pre_W, pre_b, gcn_W, gcn_b,
                              coeff_W, coeff_b, out_sf, out_ori);
    buildW_kernel<<<(2 * NC * NC + 255) / 256, 256>>>(bases);

    const int AGG_GRID  = (2 * N_NODES * 32 + 255) / 256;
    const int GEMM_GRID = (N_NODES + 127) / 128;

    // ---- layer 0 (outputs only needed as fp16 for layer 1) ----
    agg_all_kernel<<<AGG_GRID, 256>>>(p_ha, p_hb, p_mid_a, p_mid_b);
    gemm_ln_kernel<256, 1><<<GEMM_GRID, 256, SMEM_GEMM>>>(
        p_mid_a, p_Wcat, sage_bias + 1 * NC, sage_bias + 2 * NC,
        ln_w + 0 * NC, ln_b + 0 * NC, nullptr, p_ha, N_NODES);
    gemm_ln_kernel<128, 1><<<GEMM_GRID, 256, SMEM_GEMM>>>(
        p_mid_b, p_Wab, sage_bias + 0 * NC, nullptr,
        ln_w + 1 * NC, ln_b + 1 * NC, nullptr, p_hb, N_NODES);

    // ---- layer 1 (fp32 outputs to d_out) ----
    agg_all_kernel<<<AGG_GRID, 256>>>(p_ha, p_hb, p_mid_a, p_mid_b);
    gemm_ln_kernel<256, 0><<<GEMM_GRID, 256, SMEM_GEMM>>>(
        p_mid_a, p_Wcat + NC * 256, sage_bias + 4 * NC, sage_bias + 5 * NC,
        ln_w + 2 * NC, ln_b + 2 * NC, out_xa, nullptr, N_NODES);
    gemm_ln_kernel<128, 0><<<GEMM_GRID, 256, SMEM_GEMM>>>(
        p_mid_b, p_Wab + NC * NC, sage_bias + 3 * NC, nullptr,
        ln_w + 3 * NC, ln_b + 3 * NC, out_xb, nullptr, N_NODES);
}